// round 1
// baseline (speedup 1.0000x reference)
#include <cuda_runtime.h>
#include <cuda_bf16.h>
#include <cstdint>

#define BDIM 2048
#define PDIM 4096
#define PD_TP 4086
#define CONS 10
#define QDIM 1024
#define ND 192   // 64 (cw1) + 128 (ow1[:P])

// ---------------- device scratch (allocation-free) ----------------
__device__ __align__(256) float          g_m[PDIM];
__device__ __align__(256) float          g_params[(size_t)BDIM * PDIM];
__device__ __align__(256) __nv_bfloat16  g_pbf[(size_t)BDIM * PDIM];
// WA: [kp][n][ki] panels, kp = PDIM/16, n = 192, ki = 16
__device__ __align__(256) __nv_bfloat16  g_WA[(size_t)PDIM * ND];
// WB: [kp][n][ki] panels, kp = ND/16 = 12, n = 4096, ki = 16
__device__ __align__(256) __nv_bfloat16  g_WB[(size_t)ND * PDIM];
__device__ __align__(256) float          g_acc[(size_t)BDIM * ND];
__device__ __align__(256) __nv_bfloat16  g_dcat[(size_t)BDIM * ND];

// ---------------- small helpers ----------------
__device__ __forceinline__ void cp16(void* s, const void* g) {
    uint32_t sa = (uint32_t)__cvta_generic_to_shared(s);
    asm volatile("cp.async.cg.shared.global [%0], [%1], 16;\n" :: "r"(sa), "l"(g));
}
__device__ __forceinline__ void cp_commit() { asm volatile("cp.async.commit_group;\n"); }
__device__ __forceinline__ void cp_wait1()  { asm volatile("cp.async.wait_group 1;\n"); }
__device__ __forceinline__ void cp_wait0()  { asm volatile("cp.async.wait_group 0;\n"); }

__device__ __forceinline__ void mma_bf16(float* c, const uint32_t* a, const uint32_t* b) {
    asm volatile(
        "mma.sync.aligned.m16n8k16.row.col.f32.bf16.bf16.f32 "
        "{%0,%1,%2,%3},{%4,%5,%6,%7},{%8,%9},{%0,%1,%2,%3};\n"
        : "+f"(c[0]), "+f"(c[1]), "+f"(c[2]), "+f"(c[3])
        : "r"(a[0]), "r"(a[1]), "r"(a[2]), "r"(a[3]), "r"(b[0]), "r"(b[1]));
}

// ---------------- setup kernels ----------------
__global__ void k_zero_m() {
    int i = blockIdx.x * 256 + threadIdx.x;
    if (i < PDIM) g_m[i] = 0.f;
}

__global__ void k_zero_acc() {
    int i = blockIdx.x * 256 + threadIdx.x;
    if (i < BDIM * ND) g_acc[i] = 0.f;
}

// column mean of measure_proj [QDIM, PDIM], q-split with atomics
__global__ void k_colmean(const float* __restrict__ mp) {
    int p = blockIdx.x * 256 + threadIdx.x;      // 16 blocks in x -> 4096
    int q0 = blockIdx.y * (QDIM / 8);            // 8 chunks of 128
    float s = 0.f;
    #pragma unroll 4
    for (int q = 0; q < QDIM / 8; q++) s += mp[(size_t)(q0 + q) * PDIM + p];
    atomicAdd(&g_m[p], s * (1.0f / QDIM));
}

// build bf16 weight panels
__global__ void k_prepw(const float* __restrict__ cw1, const float* __restrict__ ow1) {
    int idx = blockIdx.x * 256 + threadIdx.x;
    const int NA = PDIM * ND;   // 786432
    if (idx < NA) {
        int kp = idx / (ND * 16); int rem = idx % (ND * 16);
        int n = rem >> 4; int ki = rem & 15;
        int k = kp * 16 + ki;
        float v = (n < 64) ? cw1[k * 64 + n] : ow1[k * 128 + (n - 64)];
        g_WA[idx] = __float2bfloat16(v);
    } else {
        int j = idx - NA;       // WB: 192*4096 = 786432
        int kp = j / (PDIM * 16); int rem = j % (PDIM * 16);
        int n = rem >> 4; int ki = rem & 15;
        int k = kp * 16 + ki;
        float v = (k < 128) ? ow1[n * 128 + k] : cw1[n * 64 + (k - 128)];
        g_WB[j] = __float2bfloat16(v);
    }
}

// params0 = tanh(0.7*colmean + 0.3*enc)
__global__ void k_init(const float* __restrict__ tp, const float* __restrict__ cons) {
    int idx = blockIdx.x * 256 + threadIdx.x;   // 2048*4096 total
    int b = idx >> 12;
    int p = idx & (PDIM - 1);
    float enc = (p < PD_TP) ? tp[(size_t)b * PD_TP + p] : cons[b * CONS + (p - PD_TP)];
    float v = tanhf(0.7f * g_m[p] + 0.3f * enc);
    g_params[idx] = v;
    g_pbf[idx] = __float2bfloat16(v);
}

// ---------------- GEMM1: acc[2048,192] += pbf[2048,4096] x WA[4096,192], split-K=8 ----------------
__global__ void __launch_bounds__(256) k_gemm1() {
    __shared__ __nv_bfloat16 sA[2][128 * 16];
    __shared__ __nv_bfloat16 sB[2][ND * 16];
    const int tid = threadIdx.x, lane = tid & 31, w = tid >> 5;
    const int wm = w >> 1, wn = w & 1, g = lane >> 2, tg = lane & 3;
    const int m0 = blockIdx.x * 128;
    const int k0 = blockIdx.y * 512;            // K chunk of 512 (32 steps of 16)
    const int arow = tid >> 1, acb = (tid & 1) * 8;

    float acc[2][12][4];
    #pragma unroll
    for (int i = 0; i < 2; i++)
        #pragma unroll
        for (int j = 0; j < 12; j++)
            #pragma unroll
            for (int q = 0; q < 4; q++) acc[i][j][q] = 0.f;

    // preload tile 0
    cp16(&sA[0][arow * 16 + acb], &g_pbf[(size_t)(m0 + arow) * PDIM + k0 + acb]);
    {
        const __nv_bfloat16* src = &g_WA[(size_t)(k0 >> 4) * ND * 16];
        cp16(&sB[0][tid * 8], src + tid * 8);
        if (tid < 128) cp16(&sB[0][2048 + tid * 8], src + 2048 + tid * 8);
    }
    cp_commit();

    for (int s = 0; s < 32; s++) {
        int buf = s & 1;
        if (s + 1 < 32) {
            int nb = buf ^ 1;
            cp16(&sA[nb][arow * 16 + acb],
                 &g_pbf[(size_t)(m0 + arow) * PDIM + k0 + (s + 1) * 16 + acb]);
            const __nv_bfloat16* src = &g_WA[(size_t)((k0 >> 4) + s + 1) * ND * 16];
            cp16(&sB[nb][tid * 8], src + tid * 8);
            if (tid < 128) cp16(&sB[nb][2048 + tid * 8], src + 2048 + tid * 8);
            cp_commit();
            cp_wait1();
        } else {
            cp_wait0();
        }
        __syncthreads();

        uint32_t afr[2][4];
        #pragma unroll
        for (int mf = 0; mf < 2; mf++) {
            const __nv_bfloat16* base = &sA[buf][(wm * 32 + mf * 16 + g) * 16];
            afr[mf][0] = *(const uint32_t*)(base + tg * 2);
            afr[mf][1] = *(const uint32_t*)(base + 128 + tg * 2);
            afr[mf][2] = *(const uint32_t*)(base + tg * 2 + 8);
            afr[mf][3] = *(const uint32_t*)(base + 128 + tg * 2 + 8);
        }
        #pragma unroll
        for (int nf = 0; nf < 12; nf++) {
            const __nv_bfloat16* bb = &sB[buf][(wn * 96 + nf * 8 + g) * 16];
            uint32_t bfr[2];
            bfr[0] = *(const uint32_t*)(bb + tg * 2);
            bfr[1] = *(const uint32_t*)(bb + tg * 2 + 8);
            mma_bf16(acc[0][nf], afr[0], bfr);
            mma_bf16(acc[1][nf], afr[1], bfr);
        }
        __syncthreads();
    }

    #pragma unroll
    for (int mf = 0; mf < 2; mf++)
        #pragma unroll
        for (int nf = 0; nf < 12; nf++) {
            int r = m0 + wm * 32 + mf * 16 + g;
            int c = wn * 96 + nf * 8 + tg * 2;
            atomicAdd(&g_acc[r * ND + c],           acc[mf][nf][0]);
            atomicAdd(&g_acc[r * ND + c + 1],       acc[mf][nf][1]);
            atomicAdd(&g_acc[(r + 8) * ND + c],     acc[mf][nf][2]);
            atomicAdd(&g_acc[(r + 8) * ND + c + 1], acc[mf][nf][3]);
        }
}

// ---------------- per-row MLP forward + backward (small) ----------------
__global__ void __launch_bounds__(128) k_finish(
    const float* __restrict__ cb1, const float* __restrict__ cw2,
    const float* __restrict__ cb2, const float* __restrict__ ow1,
    const float* __restrict__ ob1, const float* __restrict__ ow2,
    const float* __restrict__ ob2, const float* __restrict__ ow3) {
    __shared__ float s_acc[192];
    __shared__ float s_z1c[64], s_h1c[64], s_cv[10];
    __shared__ float s_z1[128], s_a1[128];
    __shared__ float s_dz2[64], s_dz1[128], s_dzc[10];

    const int b = blockIdx.x, t = threadIdx.x;
    for (int i = t; i < 192; i += 128) s_acc[i] = g_acc[b * ND + i];
    __syncthreads();

    if (t < 64) {
        float z = s_acc[t] + cb1[t];
        s_z1c[t] = z; s_h1c[t] = fmaxf(z, 0.f);
    }
    __syncthreads();

    if (t < 10) {
        float s = cb2[t];
        #pragma unroll 8
        for (int k = 0; k < 64; k++) s += s_h1c[k] * cw2[k * 10 + t];
        s_cv[t] = 1.f / (1.f + expf(-s));
    }
    __syncthreads();

    {
        float z = s_acc[64 + t] + ob1[t];
        #pragma unroll
        for (int i = 0; i < 10; i++) z += s_cv[i] * ow1[(PDIM + i) * 128 + t];
        s_z1[t] = z; s_a1[t] = fmaxf(z, 0.f);
    }
    __syncthreads();

    if (t < 64) {
        float s = ob2[t];
        #pragma unroll 8
        for (int j = 0; j < 128; j++) s += s_a1[j] * ow2[j * 64 + t];
        s_dz2[t] = (s > 0.f) ? ow3[t] : 0.f;
    }
    __syncthreads();

    {
        float s = 0.f;
        #pragma unroll 8
        for (int k = 0; k < 64; k++) s += s_dz2[k] * ow2[t * 64 + k];
        float d = (s_z1[t] > 0.f) ? s : 0.f;
        s_dz1[t] = d;
        g_dcat[(size_t)b * ND + t] = __float2bfloat16(d);
    }
    __syncthreads();

    if (t < 10) {
        float s = 0.f;
        #pragma unroll 8
        for (int j = 0; j < 128; j++) s += s_dz1[j] * ow1[(PDIM + t) * 128 + j];
        s_dzc[t] = s * s_cv[t] * (1.f - s_cv[t]);
    }
    __syncthreads();

    if (t < 64) {
        float s = 0.f;
        #pragma unroll
        for (int i = 0; i < 10; i++) s += s_dzc[i] * cw2[t * 10 + i];
        float d = (s_z1c[t] > 0.f) ? s : 0.f;
        g_dcat[(size_t)b * ND + 128 + t] = __float2bfloat16(d);
    }
}

// ---------------- GEMM2: g = dcat[2048,192] x WB[192,4096]; params -= 0.01*g ----------------
__global__ void __launch_bounds__(256) k_gemm2(float* __restrict__ outp, int last) {
    __shared__ __nv_bfloat16 sA[2][128 * 16];
    __shared__ __nv_bfloat16 sB[2][128 * 16];
    const int tid = threadIdx.x, lane = tid & 31, w = tid >> 5;
    const int wm = w >> 1, wn = w & 1, g = lane >> 2, tg = lane & 3;
    const int m0 = blockIdx.x * 128;
    const int n0 = blockIdx.y * 128;
    const int arow = tid >> 1, acb = (tid & 1) * 8;
    const int bk = tid >> 4, bnv = tid & 15;   // B tile: k = tid/16, n-vec = tid%16

    float acc[2][8][4];
    #pragma unroll
    for (int i = 0; i < 2; i++)
        #pragma unroll
        for (int j = 0; j < 8; j++)
            #pragma unroll
            for (int q = 0; q < 4; q++) acc[i][j][q] = 0.f;
    (void)bk; (void)bnv;

    cp16(&sA[0][arow * 16 + acb], &g_dcat[(size_t)(m0 + arow) * ND + acb]);
    cp16(&sB[0][tid * 8], &g_WB[(size_t)n0 * 16 + tid * 8]);
    cp_commit();

    for (int s = 0; s < 12; s++) {
        int buf = s & 1;
        if (s + 1 < 12) {
            int nb = buf ^ 1;
            cp16(&sA[nb][arow * 16 + acb],
                 &g_dcat[(size_t)(m0 + arow) * ND + (s + 1) * 16 + acb]);
            cp16(&sB[nb][tid * 8],
                 &g_WB[(size_t)(s + 1) * PDIM * 16 + (size_t)n0 * 16 + tid * 8]);
            cp_commit();
            cp_wait1();
        } else {
            cp_wait0();
        }
        __syncthreads();

        uint32_t afr[2][4];
        #pragma unroll
        for (int mf = 0; mf < 2; mf++) {
            const __nv_bfloat16* base = &sA[buf][(wm * 32 + mf * 16 + g) * 16];
            afr[mf][0] = *(const uint32_t*)(base + tg * 2);
            afr[mf][1] = *(const uint32_t*)(base + 128 + tg * 2);
            afr[mf][2] = *(const uint32_t*)(base + tg * 2 + 8);
            afr[mf][3] = *(const uint32_t*)(base + 128 + tg * 2 + 8);
        }
        #pragma unroll
        for (int nf = 0; nf < 8; nf++) {
            const __nv_bfloat16* bb = &sB[buf][(wn * 64 + nf * 8 + g) * 16];
            uint32_t bfr[2];
            bfr[0] = *(const uint32_t*)(bb + tg * 2);
            bfr[1] = *(const uint32_t*)(bb + tg * 2 + 8);
            mma_bf16(acc[0][nf], afr[0], bfr);
            mma_bf16(acc[1][nf], afr[1], bfr);
        }
        __syncthreads();
    }

    // epilogue: params -= 0.01*g ; last step writes d_out instead
    #pragma unroll
    for (int mf = 0; mf < 2; mf++)
        #pragma unroll
        for (int nf = 0; nf < 8; nf++) {
            int r = m0 + wm * 32 + mf * 16 + g;
            int c = n0 + wn * 64 + nf * 8 + tg * 2;
            size_t i0 = (size_t)r * PDIM + c;
            size_t i1 = i0 + (size_t)8 * PDIM;
            float2 pv0 = *(const float2*)&g_params[i0];
            float2 pv1 = *(const float2*)&g_params[i1];
            float p00 = pv0.x - 0.01f * acc[mf][nf][0];
            float p01 = pv0.y - 0.01f * acc[mf][nf][1];
            float p10 = pv1.x - 0.01f * acc[mf][nf][2];
            float p11 = pv1.y - 0.01f * acc[mf][nf][3];
            if (last) {
                *(float2*)&outp[i0] = make_float2(p00, p01);
                *(float2*)&outp[i1] = make_float2(p10, p11);
            } else {
                *(float2*)&g_params[i0] = make_float2(p00, p01);
                *(float2*)&g_params[i1] = make_float2(p10, p11);
                *(__nv_bfloat162*)&g_pbf[i0] = __nv_bfloat162(__float2bfloat16(p00), __float2bfloat16(p01));
                *(__nv_bfloat162*)&g_pbf[i1] = __nv_bfloat162(__float2bfloat16(p10), __float2bfloat16(p11));
            }
        }
}

// ---------------- launch ----------------
extern "C" void kernel_launch(void* const* d_in, const int* in_sizes, int n_in,
                              void* d_out, int out_size) {
    const float* tp   = (const float*)d_in[0];
    const float* cons = (const float*)d_in[1];
    // d_in[2] transverse_field : dead (annealing loop is identity on uniform state)
    // d_in[3] coupling         : dead (only feeds the per-row scalar energy)
    const float* mp   = (const float*)d_in[4];
    const float* cw1  = (const float*)d_in[5];
    const float* cb1  = (const float*)d_in[6];
    const float* cw2  = (const float*)d_in[7];
    const float* cb2  = (const float*)d_in[8];
    const float* ow1  = (const float*)d_in[9];
    const float* ob1  = (const float*)d_in[10];
    const float* ow2  = (const float*)d_in[11];
    const float* ob2  = (const float*)d_in[12];
    const float* ow3  = (const float*)d_in[13];
    // d_in[14] ob3 : constant offset, no gradient -> dead
    float* outp = (float*)d_out;

    k_zero_m<<<16, 256>>>();
    k_colmean<<<dim3(16, 8), 256>>>(mp);
    k_prepw<<<(2 * PDIM * ND) / 256, 256>>>(cw1, ow1);
    k_init<<<(BDIM * PDIM) / 256, 256>>>(tp, cons);

    for (int step = 0; step < 3; step++) {
        k_zero_acc<<<(BDIM * ND) / 256, 256>>>();
        k_gemm1<<<dim3(16, 8), 256>>>();
        k_finish<<<BDIM, 128>>>(cb1, cw2, cb2, ow1, ob1, ow2, ob2, ow3);
        k_gemm2<<<dim3(16, 32), 256>>>(outp, step == 2 ? 1 : 0);
    }
}

// round 2
// speedup vs baseline: 1.0819x; 1.0819x over previous
#include <cuda_runtime.h>
#include <cuda_bf16.h>
#include <cstdint>

#define BDIM 2048
#define PDIM 4096
#define PD_TP 4086
#define CONS 10
#define QDIM 1024
#define ND 192          // 64 (cw1) + 128 (ow1[:P])
#define SK2 200         // gemm2 smem/global padded k-stride (elems)
#define SKA 40          // gemm1 smem k-stride for k=32 stages (elems)
#define NSPLIT 8        // gemm1 split-K

// ---------------- device scratch (allocation-free) ----------------
__device__ __align__(256) float          g_m[PDIM];
__device__ __align__(256) float          g_params[(size_t)BDIM * PDIM];
__device__ __align__(256) __nv_bfloat16  g_pbf[(size_t)BDIM * PDIM];
__device__ __align__(256) __nv_bfloat16  g_WAt[(size_t)ND * PDIM];          // [n=192][k=4096]
__device__ __align__(256) __nv_bfloat16  g_WBt[(size_t)PDIM * SK2];         // [p=4096][k=200]
__device__ __align__(256) float          g_accp[(size_t)NSPLIT * BDIM * ND];// split-K partials
__device__ __align__(256) __nv_bfloat16  g_dcat[(size_t)BDIM * SK2];        // [b][200], pre-scaled by -0.01

// ---------------- helpers ----------------
__device__ __forceinline__ void cp16(void* s, const void* g) {
    uint32_t sa = (uint32_t)__cvta_generic_to_shared(s);
    asm volatile("cp.async.cg.shared.global [%0], [%1], 16;\n" :: "r"(sa), "l"(g));
}
__device__ __forceinline__ void cp_commit() { asm volatile("cp.async.commit_group;\n"); }
__device__ __forceinline__ void cp_wait0()  { asm volatile("cp.async.wait_group 0;\n"); }
__device__ __forceinline__ void cp_wait1()  { asm volatile("cp.async.wait_group 1;\n"); }
__device__ __forceinline__ void cp_wait2()  { asm volatile("cp.async.wait_group 2;\n"); }

__device__ __forceinline__ void mma_bf16(float* c, const uint32_t* a, const uint32_t* b) {
    asm volatile(
        "mma.sync.aligned.m16n8k16.row.col.f32.bf16.bf16.f32 "
        "{%0,%1,%2,%3},{%4,%5,%6,%7},{%8,%9},{%0,%1,%2,%3};\n"
        : "+f"(c[0]), "+f"(c[1]), "+f"(c[2]), "+f"(c[3])
        : "r"(a[0]), "r"(a[1]), "r"(a[2]), "r"(a[3]), "r"(b[0]), "r"(b[1]));
}
__device__ __forceinline__ void ldsm4(uint32_t& r0, uint32_t& r1, uint32_t& r2, uint32_t& r3,
                                      const void* p) {
    uint32_t a = (uint32_t)__cvta_generic_to_shared(p);
    asm volatile("ldmatrix.sync.aligned.m8n8.x4.shared.b16 {%0,%1,%2,%3},[%4];\n"
                 : "=r"(r0), "=r"(r1), "=r"(r2), "=r"(r3) : "r"(a));
}
__device__ __forceinline__ float ftanh(float x) {
    float y; asm("tanh.approx.f32 %0, %1;\n" : "=f"(y) : "f"(x)); return y;
}

// ---------------- setup kernels ----------------
__global__ void k_zero_m() {
    int i = blockIdx.x * 256 + threadIdx.x;
    if (i < PDIM) g_m[i] = 0.f;
}

// column mean of measure_proj [QDIM, PDIM]
__global__ void k_colmean(const float* __restrict__ mp) {
    int p = blockIdx.x * 256 + threadIdx.x;
    int q0 = blockIdx.y * (QDIM / 8);
    float s = 0.f;
    #pragma unroll 4
    for (int q = 0; q < QDIM / 8; q++) s += mp[(size_t)(q0 + q) * PDIM + p];
    atomicAdd(&g_m[p], s * (1.0f / QDIM));
}

// build row-major bf16 weight matrices for ldmatrix consumption
__global__ void k_prepw(const float* __restrict__ cw1, const float* __restrict__ ow1) {
    int idx = blockIdx.x * 256 + threadIdx.x;
    const int T1 = ND * PDIM;       // 786432
    if (idx < T1) {
        int n = idx / PDIM, k = idx % PDIM;
        float v = (n < 64) ? cw1[k * 64 + n] : ow1[k * 128 + (n - 64)];
        g_WAt[idx] = __float2bfloat16(v);
    } else {
        int j = idx - T1;           // PDIM*SK2 = 819200
        int p = j / SK2, q = j % SK2;
        float v = 0.f;
        if (q < 128)      v = ow1[p * 128 + q];
        else if (q < ND)  v = cw1[p * 64 + (q - 128)];
        g_WBt[j] = __float2bfloat16(v);
    }
}

// params0 = tanh(0.7*colmean + 0.3*enc), vectorized x4
__global__ void __launch_bounds__(256) k_init(const float* __restrict__ tp,
                                              const float* __restrict__ cons) {
    int idx = blockIdx.x * 256 + threadIdx.x;     // group of 4 elems
    int b = idx >> 10;
    int pg = (idx & 1023) << 2;
    float v[4];
    #pragma unroll
    for (int j = 0; j < 4; j++) {
        int p = pg + j;
        float enc = (p < PD_TP) ? __ldg(&tp[(size_t)b * PD_TP + p])
                                : __ldg(&cons[b * CONS + (p - PD_TP)]);
        v[j] = ftanh(0.7f * g_m[p] + 0.3f * enc);
    }
    size_t o = (size_t)b * PDIM + pg;
    *(float4*)&g_params[o] = make_float4(v[0], v[1], v[2], v[3]);
    union { __nv_bfloat162 h[2]; uint2 u; } pk;
    pk.h[0] = __floats2bfloat162_rn(v[0], v[1]);
    pk.h[1] = __floats2bfloat162_rn(v[2], v[3]);
    *(uint2*)&g_pbf[o] = pk.u;
}

// ---------------- GEMM1: accp[split] = pbf[2048,4096] x WAt^T -> [2048,192] ----------------
// grid (16 m-blocks, 8 k-splits), 256 threads, 4-stage cp.async ring, k=32/stage
__global__ void __launch_bounds__(256) k_gemm1() {
    extern __shared__ char smem_raw[];
    __nv_bfloat16* smem = (__nv_bfloat16*)smem_raw;
    // per stage: A 128*40, B 192*40 (elems)
    const int STG_E = 128 * SKA + ND * SKA;    // 12800
    const int tid = threadIdx.x, lane = tid & 31, w = tid >> 5;
    const int wm = w >> 1, wn = w & 1, g = lane >> 2, tg = lane & 3;
    const int m0 = blockIdx.x * 128;
    const int ks0 = blockIdx.y * 512;

    float acc[2][12][4];
    #pragma unroll
    for (int i = 0; i < 2; i++)
        #pragma unroll
        for (int j = 0; j < 12; j++)
            #pragma unroll
            for (int q = 0; q < 4; q++) acc[i][j][q] = 0.f;

    auto load_stage = [&](int st, int kt) {
        __nv_bfloat16* sA = smem + st * STG_E;
        __nv_bfloat16* sB = sA + 128 * SKA;
        #pragma unroll
        for (int i = 0; i < 2; i++) {               // A: 512 chunks
            int idx = tid + i * 256;
            int row = idx >> 2, ch = idx & 3;
            cp16(&sA[row * SKA + ch * 8], &g_pbf[(size_t)(m0 + row) * PDIM + kt + ch * 8]);
        }
        #pragma unroll
        for (int i = 0; i < 3; i++) {               // B: 768 chunks
            int idx = tid + i * 256;
            int row = idx >> 2, ch = idx & 3;
            cp16(&sB[row * SKA + ch * 8], &g_WAt[(size_t)row * PDIM + kt + ch * 8]);
        }
        cp_commit();
    };

    load_stage(0, ks0);
    load_stage(1, ks0 + 32);
    load_stage(2, ks0 + 64);

    const int arow = lane & 15, asel = (lane >> 4) << 3;
    const int brow = (lane & 7) + ((lane >> 4) << 3), bsel = ((lane >> 3) & 1) << 3;

    for (int it = 0; it < 16; it++) {
        if (it < 14) cp_wait2(); else if (it == 14) cp_wait1(); else cp_wait0();
        __syncthreads();
        if (it + 3 < 16) load_stage((it + 3) & 3, ks0 + (it + 3) * 32);

        __nv_bfloat16* sA = smem + (it & 3) * STG_E;
        __nv_bfloat16* sB = sA + 128 * SKA;
        #pragma unroll
        for (int ks = 0; ks < 32; ks += 16) {
            uint32_t a[2][4];
            #pragma unroll
            for (int mf = 0; mf < 2; mf++)
                ldsm4(a[mf][0], a[mf][1], a[mf][2], a[mf][3],
                      &sA[(wm * 32 + mf * 16 + arow) * SKA + ks + asel]);
            #pragma unroll
            for (int nt = 0; nt < 6; nt++) {
                uint32_t b0, b1, b2, b3;
                ldsm4(b0, b1, b2, b3,
                      &sB[(wn * 96 + nt * 16 + brow) * SKA + ks + bsel]);
                uint32_t bp0[2] = {b0, b1}, bp1[2] = {b2, b3};
                #pragma unroll
                for (int mf = 0; mf < 2; mf++) {
                    mma_bf16(acc[mf][nt * 2],     a[mf], bp0);
                    mma_bf16(acc[mf][nt * 2 + 1], a[mf], bp1);
                }
            }
        }
        __syncthreads();
    }

    float* out = &g_accp[(size_t)blockIdx.y * BDIM * ND];
    #pragma unroll
    for (int mf = 0; mf < 2; mf++)
        #pragma unroll
        for (int nf = 0; nf < 12; nf++) {
            int r = m0 + wm * 32 + mf * 16 + g;
            int c = wn * 96 + nf * 8 + tg * 2;
            *(float2*)&out[(size_t)r * ND + c]       = make_float2(acc[mf][nf][0], acc[mf][nf][1]);
            *(float2*)&out[(size_t)(r + 8) * ND + c] = make_float2(acc[mf][nf][2], acc[mf][nf][3]);
        }
}

// ---------------- per-row MLP forward + backward ----------------
__global__ void __launch_bounds__(128) k_finish(
    const float* __restrict__ cb1, const float* __restrict__ cw2,
    const float* __restrict__ cb2, const float* __restrict__ ow1,
    const float* __restrict__ ob1, const float* __restrict__ ow2,
    const float* __restrict__ ob2, const float* __restrict__ ow3) {
    __shared__ float s_acc[192];
    __shared__ float s_z1c[64], s_h1c[64], s_cv[10];
    __shared__ float s_z1[128], s_a1[128];
    __shared__ float s_dz2[64], s_dz1[128], s_dzc[10];

    const int b = blockIdx.x, t = threadIdx.x;
    for (int i = t; i < 192; i += 128) {
        float s = 0.f;
        #pragma unroll
        for (int sp = 0; sp < NSPLIT; sp++)
            s += g_accp[((size_t)sp * BDIM + b) * ND + i];
        s_acc[i] = s;
    }
    __syncthreads();

    if (t < 64) {
        float z = s_acc[128 + t] + cb1[t];   // cw1 panel lives at n in [128..192) of WBt? no:
        s_z1c[t] = z; s_h1c[t] = fmaxf(z, 0.f);
    }
    __syncthreads();

    if (t < 10) {
        float s = cb2[t];
        #pragma unroll 8
        for (int k = 0; k < 64; k++) s += s_h1c[k] * cw2[k * 10 + t];
        s_cv[t] = 1.f / (1.f + expf(-s));
    }
    __syncthreads();

    {
        float z = s_acc[64 + t] + ob1[t];
        #pragma unroll
        for (int i = 0; i < 10; i++) z += s_cv[i] * ow1[(PDIM + i) * 128 + t];
        s_z1[t] = z; s_a1[t] = fmaxf(z, 0.f);
    }
    __syncthreads();

    if (t < 64) {
        float s = ob2[t];
        #pragma unroll 8
        for (int j = 0; j < 128; j++) s += s_a1[j] * ow2[j * 64 + t];
        s_dz2[t] = (s > 0.f) ? ow3[t] : 0.f;
    }
    __syncthreads();

    {
        float s = 0.f;
        #pragma unroll 8
        for (int k = 0; k < 64; k++) s += s_dz2[k] * ow2[t * 64 + k];
        float d = (s_z1[t] > 0.f) ? s : 0.f;
        s_dz1[t] = d;
        g_dcat[(size_t)b * SK2 + t] = __float2bfloat16(-0.01f * d);
    }
    __syncthreads();

    if (t < 10) {
        float s = 0.f;
        #pragma unroll 8
        for (int j = 0; j < 128; j++) s += s_dz1[j] * ow1[(PDIM + t) * 128 + j];
        s_dzc[t] = s * s_cv[t] * (1.f - s_cv[t]);
    }
    __syncthreads();

    if (t < 64) {
        float s = 0.f;
        #pragma unroll
        for (int i = 0; i < 10; i++) s += s_dzc[i] * cw2[t * 10 + i];
        float d = (s_z1c[t] > 0.f) ? s : 0.f;
        g_dcat[(size_t)b * SK2 + 128 + t] = __float2bfloat16(-0.01f * d);
    }
    if (t < 8) g_dcat[(size_t)b * SK2 + 192 + t] = __float2bfloat16(0.f);
}

// ---------------- GEMM2: params += dcat[2048,192(-0.01-scaled)] x WBt^T ----------------
// grid (16 m, 32 n), 256 threads, full-K resident in smem, no mainloop syncs
__global__ void __launch_bounds__(256) k_gemm2(float* __restrict__ outp, int last) {
    extern __shared__ char smem_raw[];
    __nv_bfloat16* sA = (__nv_bfloat16*)smem_raw;          // 128 x 200
    __nv_bfloat16* sB = sA + 128 * SK2;                    // 128 x 200
    const int tid = threadIdx.x, lane = tid & 31, w = tid >> 5;
    const int wm = w >> 1, wn = w & 1, g = lane >> 2, tg = lane & 3;
    const int m0 = blockIdx.x * 128;
    const int n0 = blockIdx.y * 128;

    #pragma unroll
    for (int i = 0; i < 12; i++) {           // A: 3072 chunks of 16B (192 elems/row)
        int idx = tid + i * 256;
        int row = idx / 24, ch = idx % 24;
        cp16(&sA[row * SK2 + ch * 8], &g_dcat[(size_t)(m0 + row) * SK2 + ch * 8]);
    }
    #pragma unroll
    for (int i = 0; i < 12; i++) {           // B: 3072 chunks
        int idx = tid + i * 256;
        int row = idx / 24, ch = idx % 24;
        cp16(&sB[row * SK2 + ch * 8], &g_WBt[(size_t)(n0 + row) * SK2 + ch * 8]);
    }
    cp_commit();

    float acc[2][8][4];
    #pragma unroll
    for (int i = 0; i < 2; i++)
        #pragma unroll
        for (int j = 0; j < 8; j++)
            #pragma unroll
            for (int q = 0; q < 4; q++) acc[i][j][q] = 0.f;

    cp_wait0();
    __syncthreads();

    const int arow = lane & 15, asel = (lane >> 4) << 3;
    const int brow = (lane & 7) + ((lane >> 4) << 3), bsel = ((lane >> 3) & 1) << 3;

    #pragma unroll
    for (int ks = 0; ks < ND; ks += 16) {
        uint32_t a[2][4];
        #pragma unroll
        for (int mf = 0; mf < 2; mf++)
            ldsm4(a[mf][0], a[mf][1], a[mf][2], a[mf][3],
                  &sA[(wm * 32 + mf * 16 + arow) * SK2 + ks + asel]);
        #pragma unroll
        for (int nt = 0; nt < 4; nt++) {
            uint32_t b0, b1, b2, b3;
            ldsm4(b0, b1, b2, b3,
                  &sB[(wn * 64 + nt * 16 + brow) * SK2 + ks + bsel]);
            uint32_t bp0[2] = {b0, b1}, bp1[2] = {b2, b3};
            #pragma unroll
            for (int mf = 0; mf < 2; mf++) {
                mma_bf16(acc[mf][nt * 2],     a[mf], bp0);
                mma_bf16(acc[mf][nt * 2 + 1], a[mf], bp1);
            }
        }
    }

    // epilogue: params += acc (acc pre-scaled by -0.01); last step writes d_out
    #pragma unroll
    for (int mf = 0; mf < 2; mf++)
        #pragma unroll
        for (int nf = 0; nf < 8; nf++) {
            int r = m0 + wm * 32 + mf * 16 + g;
            int c = n0 + wn * 64 + nf * 8 + tg * 2;
            size_t i0 = (size_t)r * PDIM + c;
            size_t i1 = i0 + (size_t)8 * PDIM;
            float2 pv0 = *(const float2*)&g_params[i0];
            float2 pv1 = *(const float2*)&g_params[i1];
            float p00 = pv0.x + acc[mf][nf][0];
            float p01 = pv0.y + acc[mf][nf][1];
            float p10 = pv1.x + acc[mf][nf][2];
            float p11 = pv1.y + acc[mf][nf][3];
            if (last) {
                *(float2*)&outp[i0] = make_float2(p00, p01);
                *(float2*)&outp[i1] = make_float2(p10, p11);
            } else {
                *(float2*)&g_params[i0] = make_float2(p00, p01);
                *(float2*)&g_params[i1] = make_float2(p10, p11);
                *(__nv_bfloat162*)&g_pbf[i0] = __floats2bfloat162_rn(p00, p01);
                *(__nv_bfloat162*)&g_pbf[i1] = __floats2bfloat162_rn(p10, p11);
            }
        }
}

// ---------------- launch ----------------
extern "C" void kernel_launch(void* const* d_in, const int* in_sizes, int n_in,
                              void* d_out, int out_size) {
    const float* tp   = (const float*)d_in[0];
    const float* cons = (const float*)d_in[1];
    // d_in[2] transverse_field, d_in[3] coupling, d_in[14] ob3 : dead
    const float* mp   = (const float*)d_in[4];
    const float* cw1  = (const float*)d_in[5];
    const float* cb1  = (const float*)d_in[6];
    const float* cw2  = (const float*)d_in[7];
    const float* cb2  = (const float*)d_in[8];
    const float* ow1  = (const float*)d_in[9];
    const float* ob1  = (const float*)d_in[10];
    const float* ow2  = (const float*)d_in[11];
    const float* ob2  = (const float*)d_in[12];
    const float* ow3  = (const float*)d_in[13];
    float* outp = (float*)d_out;

    const int SMEM1 = 4 * (128 * SKA + ND * SKA) * 2;   // 102400
    const int SMEM2 = 2 * 128 * SK2 * 2;                // 102400
    cudaFuncSetAttribute(k_gemm1, cudaFuncAttributeMaxDynamicSharedMemorySize, SMEM1);
    cudaFuncSetAttribute(k_gemm2, cudaFuncAttributeMaxDynamicSharedMemorySize, SMEM2);

    k_zero_m<<<16, 256>>>();
    k_colmean<<<dim3(16, 8), 256>>>(mp);
    k_prepw<<<(ND * PDIM + PDIM * SK2) / 256, 256>>>(cw1, ow1);
    k_init<<<(BDIM * PDIM / 4) / 256, 256>>>(tp, cons);

    for (int step = 0; step < 3; step++) {
        k_gemm1<<<dim3(16, NSPLIT), 256, SMEM1>>>();
        k_finish<<<BDIM, 128>>>(cb1, cw2, cb2, ow1, ob1, ow2, ob2, ow3);
        k_gemm2<<<dim3(16, 32), 256, SMEM2>>>(outp, step == 2 ? 1 : 0);
    }
}

// round 3
// speedup vs baseline: 1.1234x; 1.0383x over previous
#include <cuda_runtime.h>
#include <cuda_bf16.h>
#include <cstdint>

#define BDIM 2048
#define PDIM 4096
#define PD_TP 4086
#define CONS 10
#define QDIM 1024
#define ND 192          // Wcat columns: [0,64)=cw1, [64,192)=ow1[:P]
#define SK2 200         // gemm2 padded k-stride (elems)
#define SKA 40          // gemm1 smem k-stride for k=32 stages (elems)
#define NSPLIT 8        // gemm1 split-K

// ---------------- device scratch (allocation-free) ----------------
__device__ __align__(256) float          g_m[PDIM];
__device__ __align__(256) float          g_G[ND * ND];                        // Gram WcatT*Wcat
__device__ __align__(256) float          g_params[(size_t)BDIM * PDIM];       // params0 fp32
__device__ __align__(256) __nv_bfloat16  g_pbf[(size_t)BDIM * PDIM];          // params0 bf16
__device__ __align__(256) __nv_bfloat16  g_WAt[(size_t)ND * PDIM];            // Wcat^T [n][k=4096]
__device__ __align__(256) __nv_bfloat16  g_WBt[(size_t)PDIM * SK2];           // Wcat   [p][n(pad 200)]
__device__ __align__(256) float          g_accp[(size_t)NSPLIT * BDIM * ND];  // gemm1 split-K partials
__device__ __align__(256) float          g_acc[(size_t)BDIM * ND];            // live acc_t
__device__ __align__(256) float          g_D[(size_t)BDIM * ND];              // accumulated -0.01*sum(dvec)
__device__ __align__(256) __nv_bfloat16  g_dcat[(size_t)BDIM * SK2];          // final D, bf16

// ---------------- helpers ----------------
__device__ __forceinline__ void cp16(void* s, const void* g) {
    uint32_t sa = (uint32_t)__cvta_generic_to_shared(s);
    asm volatile("cp.async.cg.shared.global [%0], [%1], 16;\n" :: "r"(sa), "l"(g));
}
__device__ __forceinline__ void cp_commit() { asm volatile("cp.async.commit_group;\n"); }
__device__ __forceinline__ void cp_wait0()  { asm volatile("cp.async.wait_group 0;\n"); }
__device__ __forceinline__ void cp_wait1()  { asm volatile("cp.async.wait_group 1;\n"); }
__device__ __forceinline__ void cp_wait2()  { asm volatile("cp.async.wait_group 2;\n"); }

__device__ __forceinline__ void mma_bf16(float* c, const uint32_t* a, const uint32_t* b) {
    asm volatile(
        "mma.sync.aligned.m16n8k16.row.col.f32.bf16.bf16.f32 "
        "{%0,%1,%2,%3},{%4,%5,%6,%7},{%8,%9},{%0,%1,%2,%3};\n"
        : "+f"(c[0]), "+f"(c[1]), "+f"(c[2]), "+f"(c[3])
        : "r"(a[0]), "r"(a[1]), "r"(a[2]), "r"(a[3]), "r"(b[0]), "r"(b[1]));
}
__device__ __forceinline__ void ldsm4(uint32_t& r0, uint32_t& r1, uint32_t& r2, uint32_t& r3,
                                      const void* p) {
    uint32_t a = (uint32_t)__cvta_generic_to_shared(p);
    asm volatile("ldmatrix.sync.aligned.m8n8.x4.shared.b16 {%0,%1,%2,%3},[%4];\n"
                 : "=r"(r0), "=r"(r1), "=r"(r2), "=r"(r3) : "r"(a));
}
__device__ __forceinline__ float ftanh(float x) {
    float y; asm("tanh.approx.f32 %0, %1;\n" : "=f"(y) : "f"(x)); return y;
}

// ---------------- setup kernels ----------------
__global__ void k_zero() {
    int i = blockIdx.x * 256 + threadIdx.x;
    if (i < PDIM) g_m[i] = 0.f;
    if (i < ND * ND) g_G[i] = 0.f;
}

// column mean of measure_proj [QDIM, PDIM]
__global__ void k_colmean(const float* __restrict__ mp) {
    int p = blockIdx.x * 256 + threadIdx.x;
    int q0 = blockIdx.y * (QDIM / 8);
    float s = 0.f;
    #pragma unroll 4
    for (int q = 0; q < QDIM / 8; q++) s += mp[(size_t)(q0 + q) * PDIM + p];
    atomicAdd(&g_m[p], s * (1.0f / QDIM));
}

// Gram matrix G = Wcat^T Wcat, fp32, split-K atomics. grid (6,6,8), 256 thr.
__global__ void __launch_bounds__(256) k_gram(const float* __restrict__ cw1,
                                              const float* __restrict__ ow1) {
    __shared__ float sA[64 * 32], sB[64 * 32];
    const int i0 = blockIdx.x * 32, j0 = blockIdx.y * 32;
    const int k0 = blockIdx.z * 512;
    const int tid = threadIdx.x, tx = tid & 15, ty = tid >> 4;
    float c[2][2] = {{0.f, 0.f}, {0.f, 0.f}};

    for (int kc = 0; kc < 8; kc++) {
        int kb = k0 + kc * 64;
        #pragma unroll
        for (int r = 0; r < 8; r++) {
            int idx = tid + r * 256;
            int kk = idx >> 5, cc = idx & 31;
            int ci = i0 + cc, cj = j0 + cc, k = kb + kk;
            sA[kk * 32 + cc] = (ci < 64) ? cw1[k * 64 + ci] : ow1[k * 128 + ci - 64];
            sB[kk * 32 + cc] = (cj < 64) ? cw1[k * 64 + cj] : ow1[k * 128 + cj - 64];
        }
        __syncthreads();
        #pragma unroll 8
        for (int k = 0; k < 64; k++) {
            float a0 = sA[k * 32 + 2 * tx], a1 = sA[k * 32 + 2 * tx + 1];
            float b0 = sB[k * 32 + 2 * ty], b1 = sB[k * 32 + 2 * ty + 1];
            c[0][0] += a0 * b0; c[0][1] += a0 * b1;
            c[1][0] += a1 * b0; c[1][1] += a1 * b1;
        }
        __syncthreads();
    }
    int gi = i0 + 2 * tx, gj = j0 + 2 * ty;
    atomicAdd(&g_G[gi * ND + gj],           c[0][0]);
    atomicAdd(&g_G[gi * ND + gj + 1],       c[0][1]);
    atomicAdd(&g_G[(gi + 1) * ND + gj],     c[1][0]);
    atomicAdd(&g_G[(gi + 1) * ND + gj + 1], c[1][1]);
}

// bf16 weight layouts: WAt = Wcat^T [n][k], WBt = Wcat [p][n] padded to SK2
__global__ void k_prepw(const float* __restrict__ cw1, const float* __restrict__ ow1) {
    int idx = blockIdx.x * 256 + threadIdx.x;
    const int T1 = ND * PDIM;       // 786432
    if (idx < T1) {
        int n = idx / PDIM, k = idx % PDIM;
        float v = (n < 64) ? cw1[k * 64 + n] : ow1[k * 128 + (n - 64)];
        g_WAt[idx] = __float2bfloat16(v);
    } else {
        int j = idx - T1;           // PDIM*SK2 = 819200
        int p = j / SK2, q = j % SK2;
        float v = 0.f;
        if (q < 64)       v = cw1[p * 64 + q];
        else if (q < ND)  v = ow1[p * 128 + (q - 64)];
        g_WBt[j] = __float2bfloat16(v);
    }
}

// params0 = tanh(0.7*colmean + 0.3*enc), float2/float4 vectorized
__global__ void __launch_bounds__(256) k_init(const float* __restrict__ tp,
                                              const float* __restrict__ cons) {
    int idx = blockIdx.x * 256 + threadIdx.x;     // one group of 4 elems
    int b = idx >> 10;
    int pg = (idx & 1023) << 2;
    const float* trow = tp + (size_t)b * PD_TP;
    float e0, e1, e2, e3;
    if (pg + 3 < PD_TP) {
        float2 u = *(const float2*)(trow + pg);
        float2 v2 = *(const float2*)(trow + pg + 2);
        e0 = u.x; e1 = u.y; e2 = v2.x; e3 = v2.y;
    } else if (pg < PD_TP) {                      // pg == 4084
        float2 u = *(const float2*)(trow + pg);
        e0 = u.x; e1 = u.y;
        e2 = cons[b * CONS + 0]; e3 = cons[b * CONS + 1];
    } else {                                      // pg = 4088 or 4092
        int c0 = pg - PD_TP;
        e0 = cons[b * CONS + c0];     e1 = cons[b * CONS + c0 + 1];
        e2 = cons[b * CONS + c0 + 2]; e3 = cons[b * CONS + c0 + 3];
    }
    float4 m4 = *(const float4*)&g_m[pg];
    float v0 = ftanh(0.7f * m4.x + 0.3f * e0);
    float v1 = ftanh(0.7f * m4.y + 0.3f * e1);
    float v2_ = ftanh(0.7f * m4.z + 0.3f * e2);
    float v3 = ftanh(0.7f * m4.w + 0.3f * e3);
    size_t o = (size_t)b * PDIM + pg;
    *(float4*)&g_params[o] = make_float4(v0, v1, v2_, v3);
    union { __nv_bfloat162 h[2]; uint2 u; } pk;
    pk.h[0] = __floats2bfloat162_rn(v0, v1);
    pk.h[1] = __floats2bfloat162_rn(v2_, v3);
    *(uint2*)&g_pbf[o] = pk.u;
}

// ---------------- GEMM1 (runs ONCE): accp = pbf x WAt^T, split-K=8 ----------------
__global__ void __launch_bounds__(256) k_gemm1() {
    extern __shared__ char smem_raw[];
    __nv_bfloat16* smem = (__nv_bfloat16*)smem_raw;
    const int STG_E = 128 * SKA + ND * SKA;    // 12800 elems/stage
    const int tid = threadIdx.x, lane = tid & 31, w = tid >> 5;
    const int wm = w >> 1, wn = w & 1, g = lane >> 2, tg = lane & 3;
    const int m0 = blockIdx.x * 128;
    const int ks0 = blockIdx.y * 512;

    float acc[2][12][4];
    #pragma unroll
    for (int i = 0; i < 2; i++)
        #pragma unroll
        for (int j = 0; j < 12; j++)
            #pragma unroll
            for (int q = 0; q < 4; q++) acc[i][j][q] = 0.f;

    auto load_stage = [&](int st, int kt) {
        __nv_bfloat16* sA = smem + st * STG_E;
        __nv_bfloat16* sB = sA + 128 * SKA;
        #pragma unroll
        for (int i = 0; i < 2; i++) {
            int idx = tid + i * 256;
            int row = idx >> 2, ch = idx & 3;
            cp16(&sA[row * SKA + ch * 8], &g_pbf[(size_t)(m0 + row) * PDIM + kt + ch * 8]);
        }
        #pragma unroll
        for (int i = 0; i < 3; i++) {
            int idx = tid + i * 256;
            int row = idx >> 2, ch = idx & 3;
            cp16(&sB[row * SKA + ch * 8], &g_WAt[(size_t)row * PDIM + kt + ch * 8]);
        }
        cp_commit();
    };

    load_stage(0, ks0);
    load_stage(1, ks0 + 32);
    load_stage(2, ks0 + 64);

    const int arow = lane & 15, asel = (lane >> 4) << 3;
    const int brow = (lane & 7) + ((lane >> 4) << 3), bsel = ((lane >> 3) & 1) << 3;

    for (int it = 0; it < 16; it++) {
        if (it < 14) cp_wait2(); else if (it == 14) cp_wait1(); else cp_wait0();
        __syncthreads();
        if (it + 3 < 16) load_stage((it + 3) & 3, ks0 + (it + 3) * 32);

        __nv_bfloat16* sA = smem + (it & 3) * STG_E;
        __nv_bfloat16* sB = sA + 128 * SKA;
        #pragma unroll
        for (int ks = 0; ks < 32; ks += 16) {
            uint32_t a[2][4];
            #pragma unroll
            for (int mf = 0; mf < 2; mf++)
                ldsm4(a[mf][0], a[mf][1], a[mf][2], a[mf][3],
                      &sA[(wm * 32 + mf * 16 + arow) * SKA + ks + asel]);
            #pragma unroll
            for (int nt = 0; nt < 6; nt++) {
                uint32_t b0, b1, b2, b3;
                ldsm4(b0, b1, b2, b3,
                      &sB[(wn * 96 + nt * 16 + brow) * SKA + ks + bsel]);
                uint32_t bp0[2] = {b0, b1}, bp1[2] = {b2, b3};
                #pragma unroll
                for (int mf = 0; mf < 2; mf++) {
                    mma_bf16(acc[mf][nt * 2],     a[mf], bp0);
                    mma_bf16(acc[mf][nt * 2 + 1], a[mf], bp1);
                }
            }
        }
        __syncthreads();
    }

    float* out = &g_accp[(size_t)blockIdx.y * BDIM * ND];
    #pragma unroll
    for (int mf = 0; mf < 2; mf++)
        #pragma unroll
        for (int nf = 0; nf < 12; nf++) {
            int r = m0 + wm * 32 + mf * 16 + g;
            int c = wn * 96 + nf * 8 + tg * 2;
            *(float2*)&out[(size_t)r * ND + c]       = make_float2(acc[mf][nf][0], acc[mf][nf][1]);
            *(float2*)&out[(size_t)(r + 8) * ND + c] = make_float2(acc[mf][nf][2], acc[mf][nf][3]);
        }
}

// ---------------- per-row backprop in 192-dim coefficient space ----------------
__global__ void __launch_bounds__(192) k_finish(
    const float* __restrict__ cb1, const float* __restrict__ cw2,
    const float* __restrict__ cb2, const float* __restrict__ ow1,
    const float* __restrict__ ob1, const float* __restrict__ ow2,
    const float* __restrict__ ob2, const float* __restrict__ ow3,
    int first, int last) {
    __shared__ float s_acc[192], s_h1c[64], s_cv[10], s_z1[128], s_a1[128];
    __shared__ float s_dz2[64], s_d[192], s_dzc[10], s_ds[192];

    const int b = blockIdx.x, t = threadIdx.x;
    if (first) {
        float s = 0.f;
        #pragma unroll
        for (int sp = 0; sp < NSPLIT; sp++)
            s += g_accp[((size_t)sp * BDIM + b) * ND + t];
        s_acc[t] = s;
    } else {
        s_acc[t] = g_acc[(size_t)b * ND + t];
    }
    __syncthreads();

    if (t < 64) { float z = s_acc[t] + cb1[t]; s_h1c[t] = fmaxf(z, 0.f); }
    __syncthreads();

    if (t < 10) {
        float s = cb2[t];
        #pragma unroll 8
        for (int k = 0; k < 64; k++) s += s_h1c[k] * cw2[k * 10 + t];
        s_cv[t] = 1.f / (1.f + expf(-s));
    }
    __syncthreads();

    if (t < 128) {
        float z = s_acc[64 + t] + ob1[t];
        #pragma unroll
        for (int i = 0; i < 10; i++) z += s_cv[i] * ow1[(PDIM + i) * 128 + t];
        s_z1[t] = z; s_a1[t] = fmaxf(z, 0.f);
    }
    __syncthreads();

    if (t < 64) {
        float s = ob2[t];
        #pragma unroll 8
        for (int j = 0; j < 128; j++) s += s_a1[j] * ow2[j * 64 + t];
        s_dz2[t] = (s > 0.f) ? ow3[t] : 0.f;
    }
    __syncthreads();

    if (t < 128) {
        float s = 0.f;
        #pragma unroll 8
        for (int k = 0; k < 64; k++) s += s_dz2[k] * ow2[t * 64 + k];
        s_d[64 + t] = (s_z1[t] > 0.f) ? s : 0.f;
    }
    __syncthreads();

    if (t < 10) {
        float s = 0.f;
        #pragma unroll 8
        for (int j = 0; j < 128; j++) s += s_d[64 + j] * ow1[(PDIM + t) * 128 + j];
        s_dzc[t] = s * s_cv[t] * (1.f - s_cv[t]);
    }
    __syncthreads();

    if (t < 64) {
        float s = 0.f;
        #pragma unroll
        for (int i = 0; i < 10; i++) s += s_dzc[i] * cw2[t * 10 + i];
        s_d[t] = (s_acc[t] + cb1[t] > 0.f) ? s : 0.f;
    }
    __syncthreads();

    float dval = -0.01f * s_d[t];
    s_ds[t] = dval;
    float Dacc = (first ? 0.f : g_D[(size_t)b * ND + t]) + dval;
    if (last) {
        g_dcat[(size_t)b * SK2 + t] = __float2bfloat16(Dacc);
    } else {
        g_D[(size_t)b * ND + t] = Dacc;
    }
    __syncthreads();

    if (!last) {
        // acc_{s+1}[n] = acc_s[n] + sum_m ds[m] * G[m][n]
        float accn = s_acc[t];
        #pragma unroll 8
        for (int m = 0; m < ND; m++) accn += s_ds[m] * g_G[m * ND + t];
        g_acc[(size_t)b * ND + t] = accn;
    }
}

// ---------------- GEMM2 (runs ONCE): out = params0 + D x Wcat^T ----------------
__global__ void __launch_bounds__(256) k_gemm2(float* __restrict__ outp) {
    extern __shared__ char smem_raw[];
    __nv_bfloat16* sA = (__nv_bfloat16*)smem_raw;          // 128 x 200
    __nv_bfloat16* sB = sA + 128 * SK2;                    // 128 x 200
    const int tid = threadIdx.x, lane = tid & 31, w = tid >> 5;
    const int wm = w >> 1, wn = w & 1, g = lane >> 2, tg = lane & 3;
    const int m0 = blockIdx.x * 128;
    const int n0 = blockIdx.y * 128;

    #pragma unroll
    for (int i = 0; i < 12; i++) {
        int idx = tid + i * 256;
        int row = idx / 24, ch = idx % 24;
        cp16(&sA[row * SK2 + ch * 8], &g_dcat[(size_t)(m0 + row) * SK2 + ch * 8]);
    }
    #pragma unroll
    for (int i = 0; i < 12; i++) {
        int idx = tid + i * 256;
        int row = idx / 24, ch = idx % 24;
        cp16(&sB[row * SK2 + ch * 8], &g_WBt[(size_t)(n0 + row) * SK2 + ch * 8]);
    }
    cp_commit();

    float acc[2][8][4];
    #pragma unroll
    for (int i = 0; i < 2; i++)
        #pragma unroll
        for (int j = 0; j < 8; j++)
            #pragma unroll
            for (int q = 0; q < 4; q++) acc[i][j][q] = 0.f;

    cp_wait0();
    __syncthreads();

    const int arow = lane & 15, asel = (lane >> 4) << 3;
    const int brow = (lane & 7) + ((lane >> 4) << 3), bsel = ((lane >> 3) & 1) << 3;

    #pragma unroll
    for (int ks = 0; ks < ND; ks += 16) {
        uint32_t a[2][4];
        #pragma unroll
        for (int mf = 0; mf < 2; mf++)
            ldsm4(a[mf][0], a[mf][1], a[mf][2], a[mf][3],
                  &sA[(wm * 32 + mf * 16 + arow) * SK2 + ks + asel]);
        #pragma unroll
        for (int nt = 0; nt < 4; nt++) {
            uint32_t b0, b1, b2, b3;
            ldsm4(b0, b1, b2, b3,
                  &sB[(wn * 64 + nt * 16 + brow) * SK2 + ks + bsel]);
            uint32_t bp0[2] = {b0, b1}, bp1[2] = {b2, b3};
            #pragma unroll
            for (int mf = 0; mf < 2; mf++) {
                mma_bf16(acc[mf][nt * 2],     a[mf], bp0);
                mma_bf16(acc[mf][nt * 2 + 1], a[mf], bp1);
            }
        }
    }

    #pragma unroll
    for (int mf = 0; mf < 2; mf++)
        #pragma unroll
        for (int nf = 0; nf < 8; nf++) {
            int r = m0 + wm * 32 + mf * 16 + g;
            int c = n0 + wn * 64 + nf * 8 + tg * 2;
            size_t i0 = (size_t)r * PDIM + c;
            size_t i1 = i0 + (size_t)8 * PDIM;
            float2 pv0 = *(const float2*)&g_params[i0];
            float2 pv1 = *(const float2*)&g_params[i1];
            *(float2*)&outp[i0] = make_float2(pv0.x + acc[mf][nf][0], pv0.y + acc[mf][nf][1]);
            *(float2*)&outp[i1] = make_float2(pv1.x + acc[mf][nf][2], pv1.y + acc[mf][nf][3]);
        }
}

// ---------------- launch ----------------
extern "C" void kernel_launch(void* const* d_in, const int* in_sizes, int n_in,
                              void* d_out, int out_size) {
    const float* tp   = (const float*)d_in[0];
    const float* cons = (const float*)d_in[1];
    // d_in[2] transverse_field, d_in[3] coupling, d_in[14] ob3 : dead
    const float* mp   = (const float*)d_in[4];
    const float* cw1  = (const float*)d_in[5];
    const float* cb1  = (const float*)d_in[6];
    const float* cw2  = (const float*)d_in[7];
    const float* cb2  = (const float*)d_in[8];
    const float* ow1  = (const float*)d_in[9];
    const float* ob1  = (const float*)d_in[10];
    const float* ow2  = (const float*)d_in[11];
    const float* ob2  = (const float*)d_in[12];
    const float* ow3  = (const float*)d_in[13];
    float* outp = (float*)d_out;

    const int SMEM1 = 4 * (128 * SKA + ND * SKA) * 2;   // 102400
    const int SMEM2 = 2 * 128 * SK2 * 2;                // 102400
    cudaFuncSetAttribute(k_gemm1, cudaFuncAttributeMaxDynamicSharedMemorySize, SMEM1);
    cudaFuncSetAttribute(k_gemm2, cudaFuncAttributeMaxDynamicSharedMemorySize, SMEM2);

    k_zero<<<(ND * ND + 255) / 256, 256>>>();
    k_colmean<<<dim3(16, 8), 256>>>(mp);
    k_gram<<<dim3(6, 6, 8), 256>>>(cw1, ow1);
    k_prepw<<<(ND * PDIM + PDIM * SK2) / 256, 256>>>(cw1, ow1);
    k_init<<<(BDIM * PDIM / 4) / 256, 256>>>(tp, cons);

    k_gemm1<<<dim3(16, NSPLIT), 256, SMEM1>>>();
    k_finish<<<BDIM, 192>>>(cb1, cw2, cb2, ow1, ob1, ow2, ob2, ow3, 1, 0);
    k_finish<<<BDIM, 192>>>(cb1, cw2, cb2, ow1, ob1, ow2, ob2, ow3, 0, 0);
    k_finish<<<BDIM, 192>>>(cb1, cw2, cb2, ow1, ob1, ow2, ob2, ow3, 0, 1);
    k_gemm2<<<dim3(16, 32), 256, SMEM2>>>(outp);
}

// round 4
// speedup vs baseline: 1.6493x; 1.4682x over previous
#include <cuda_runtime.h>
#include <cuda_bf16.h>
#include <cstdint>

#define BDIM 2048
#define PDIM 4096
#define PD_TP 4086
#define CONS 10
#define QDIM 1024
#define ND 192          // Wcat columns: [0,64)=cw1, [64,192)=ow1[:P]
#define SK2 200         // gemm2 padded k-stride (elems)
#define SKA 40          // gemm1 smem k-stride (elems)
#define NSPLIT 8        // gemm1 split-K
#define FR 16           // finish3 rows per block

// ---------------- device scratch (allocation-free) ----------------
__device__ __align__(256) float          g_m[PDIM];
__device__ __align__(256) float          g_G[ND * ND];                        // Gram Wcat^T Wcat
__device__ __align__(256) float          g_params[(size_t)BDIM * PDIM];       // params0 fp32
__device__ __align__(256) __nv_bfloat16  g_pbf[(size_t)BDIM * PDIM];          // params0 bf16
__device__ __align__(256) __nv_bfloat16  g_WAt[(size_t)ND * PDIM];            // Wcat^T [n][k]
__device__ __align__(256) __nv_bfloat16  g_WBt[(size_t)PDIM * SK2];           // Wcat   [p][n pad]
__device__ __align__(256) float          g_accp[(size_t)NSPLIT * BDIM * ND];  // gemm1 partials
__device__ __align__(256) __nv_bfloat16  g_dcat[(size_t)BDIM * SK2];          // final D bf16

// ---------------- helpers ----------------
__device__ __forceinline__ void cp16(void* s, const void* g) {
    uint32_t sa = (uint32_t)__cvta_generic_to_shared(s);
    asm volatile("cp.async.cg.shared.global [%0], [%1], 16;\n" :: "r"(sa), "l"(g));
}
__device__ __forceinline__ void cp_commit() { asm volatile("cp.async.commit_group;\n"); }
__device__ __forceinline__ void cp_wait0()  { asm volatile("cp.async.wait_group 0;\n"); }
__device__ __forceinline__ void cp_wait1()  { asm volatile("cp.async.wait_group 1;\n"); }
__device__ __forceinline__ void cp_wait2()  { asm volatile("cp.async.wait_group 2;\n"); }

__device__ __forceinline__ void mma_bf16(float* c, const uint32_t* a, const uint32_t* b) {
    asm volatile(
        "mma.sync.aligned.m16n8k16.row.col.f32.bf16.bf16.f32 "
        "{%0,%1,%2,%3},{%4,%5,%6,%7},{%8,%9},{%0,%1,%2,%3};\n"
        : "+f"(c[0]), "+f"(c[1]), "+f"(c[2]), "+f"(c[3])
        : "r"(a[0]), "r"(a[1]), "r"(a[2]), "r"(a[3]), "r"(b[0]), "r"(b[1]));
}
__device__ __forceinline__ void ldsm4(uint32_t& r0, uint32_t& r1, uint32_t& r2, uint32_t& r3,
                                      const void* p) {
    uint32_t a = (uint32_t)__cvta_generic_to_shared(p);
    asm volatile("ldmatrix.sync.aligned.m8n8.x4.shared.b16 {%0,%1,%2,%3},[%4];\n"
                 : "=r"(r0), "=r"(r1), "=r"(r2), "=r"(r3) : "r"(a));
}
__device__ __forceinline__ float ftanh(float x) {
    float y; asm("tanh.approx.f32 %0, %1;\n" : "=f"(y) : "f"(x)); return y;
}

// ---------------- k_setup: colmean + gram + prepw in one launch ----------------
// blocks [0,128): colmean (32 p's each, block-reduced, direct g_m write)
// blocks [128,164): gram 32x32 tiles, full K, no atomics
// blocks [164, 164+6272): prepw
#define NB_CM   128
#define NB_GRAM 36
#define NB_PREP 6272
__global__ void __launch_bounds__(256) k_setup(const float* __restrict__ mp,
                                               const float* __restrict__ cw1,
                                               const float* __restrict__ ow1) {
    __shared__ float sbuf[4096];
    const int blk = blockIdx.x, tid = threadIdx.x;

    if (blk < NB_CM) {
        // ---- column mean of measure_proj ----
        int p = blk * 32 + (tid & 31);
        int qi = tid >> 5;                    // 0..7
        float s = 0.f;
        #pragma unroll 8
        for (int q = qi * 128; q < qi * 128 + 128; q++)
            s += mp[(size_t)q * PDIM + p];
        sbuf[qi * 32 + (tid & 31)] = s;
        __syncthreads();
        if (tid < 32) {
            float t = 0.f;
            #pragma unroll
            for (int r = 0; r < 8; r++) t += sbuf[r * 32 + tid];
            g_m[blk * 32 + tid] = t * (1.0f / QDIM);
        }
        return;
    }

    if (blk < NB_CM + NB_GRAM) {
        // ---- Gram: G = Wcat^T Wcat, one 32x32 tile per block, full K ----
        float* sA = sbuf;              // 64 x 32
        float* sB = sbuf + 2048;       // 64 x 32
        int gb = blk - NB_CM;
        int i0 = (gb / 6) * 32, j0 = (gb % 6) * 32;
        int tx = tid & 15, ty = tid >> 4;
        float c00 = 0.f, c01 = 0.f, c10 = 0.f, c11 = 0.f;
        for (int kc = 0; kc < 64; kc++) {
            int kb = kc * 64;
            #pragma unroll
            for (int r = 0; r < 8; r++) {
                int idx = tid + r * 256;
                int kk = idx >> 5, cc = idx & 31;
                int ci = i0 + cc, cj = j0 + cc, k = kb + kk;
                sA[kk * 32 + cc] = (ci < 64) ? cw1[k * 64 + ci] : ow1[k * 128 + ci - 64];
                sB[kk * 32 + cc] = (cj < 64) ? cw1[k * 64 + cj] : ow1[k * 128 + cj - 64];
            }
            __syncthreads();
            #pragma unroll 8
            for (int k = 0; k < 64; k++) {
                float a0 = sA[k * 32 + 2 * tx], a1 = sA[k * 32 + 2 * tx + 1];
                float b0 = sB[k * 32 + 2 * ty], b1 = sB[k * 32 + 2 * ty + 1];
                c00 += a0 * b0; c01 += a0 * b1;
                c10 += a1 * b0; c11 += a1 * b1;
            }
            __syncthreads();
        }
        int gi = i0 + 2 * tx, gj = j0 + 2 * ty;
        g_G[gi * ND + gj]           = c00;
        g_G[gi * ND + gj + 1]       = c01;
        g_G[(gi + 1) * ND + gj]     = c10;
        g_G[(gi + 1) * ND + gj + 1] = c11;
        return;
    }

    // ---- prepw: bf16 weight layouts ----
    int idx = (blk - NB_CM - NB_GRAM) * 256 + tid;
    const int T1 = ND * PDIM;       // 786432
    if (idx < T1) {
        int n = idx / PDIM, k = idx % PDIM;
        float v = (n < 64) ? cw1[k * 64 + n] : ow1[k * 128 + (n - 64)];
        g_WAt[idx] = __float2bfloat16(v);
    } else {
        int j = idx - T1;           // PDIM*SK2 = 819200
        int p = j / SK2, q = j % SK2;
        float v = 0.f;
        if (q < 64)       v = cw1[p * 64 + q];
        else if (q < ND)  v = ow1[p * 128 + (q - 64)];
        g_WBt[j] = __float2bfloat16(v);
    }
}

// ---------------- params0 = tanh(0.7*colmean + 0.3*enc) ----------------
__global__ void __launch_bounds__(256) k_init(const float* __restrict__ tp,
                                              const float* __restrict__ cons) {
    int idx = blockIdx.x * 256 + threadIdx.x;
    int b = idx >> 10;
    int pg = (idx & 1023) << 2;
    const float* trow = tp + (size_t)b * PD_TP;
    float e0, e1, e2, e3;
    if (pg + 3 < PD_TP) {
        float2 u = *(const float2*)(trow + pg);
        float2 v2 = *(const float2*)(trow + pg + 2);
        e0 = u.x; e1 = u.y; e2 = v2.x; e3 = v2.y;
    } else if (pg < PD_TP) {                      // pg == 4084
        float2 u = *(const float2*)(trow + pg);
        e0 = u.x; e1 = u.y;
        e2 = cons[b * CONS + 0]; e3 = cons[b * CONS + 1];
    } else {
        int c0 = pg - PD_TP;
        e0 = cons[b * CONS + c0];     e1 = cons[b * CONS + c0 + 1];
        e2 = cons[b * CONS + c0 + 2]; e3 = cons[b * CONS + c0 + 3];
    }
    float4 m4 = *(const float4*)&g_m[pg];
    float v0 = ftanh(0.7f * m4.x + 0.3f * e0);
    float v1 = ftanh(0.7f * m4.y + 0.3f * e1);
    float v2_ = ftanh(0.7f * m4.z + 0.3f * e2);
    float v3 = ftanh(0.7f * m4.w + 0.3f * e3);
    size_t o = (size_t)b * PDIM + pg;
    *(float4*)&g_params[o] = make_float4(v0, v1, v2_, v3);
    union { __nv_bfloat162 h[2]; uint2 u; } pk;
    pk.h[0] = __floats2bfloat162_rn(v0, v1);
    pk.h[1] = __floats2bfloat162_rn(v2_, v3);
    *(uint2*)&g_pbf[o] = pk.u;
}

// ---------------- GEMM1: accp = pbf x WAt^T, split-K=8 ----------------
__global__ void __launch_bounds__(256) k_gemm1() {
    extern __shared__ char smem_raw[];
    __nv_bfloat16* smem = (__nv_bfloat16*)smem_raw;
    const int STG_E = 128 * SKA + ND * SKA;
    const int tid = threadIdx.x, lane = tid & 31, w = tid >> 5;
    const int wm = w >> 1, wn = w & 1, g = lane >> 2, tg = lane & 3;
    const int m0 = blockIdx.x * 128;
    const int ks0 = blockIdx.y * 512;

    float acc[2][12][4];
    #pragma unroll
    for (int i = 0; i < 2; i++)
        #pragma unroll
        for (int j = 0; j < 12; j++)
            #pragma unroll
            for (int q = 0; q < 4; q++) acc[i][j][q] = 0.f;

    auto load_stage = [&](int st, int kt) {
        __nv_bfloat16* sA = smem + st * STG_E;
        __nv_bfloat16* sB = sA + 128 * SKA;
        #pragma unroll
        for (int i = 0; i < 2; i++) {
            int idx = tid + i * 256;
            int row = idx >> 2, ch = idx & 3;
            cp16(&sA[row * SKA + ch * 8], &g_pbf[(size_t)(m0 + row) * PDIM + kt + ch * 8]);
        }
        #pragma unroll
        for (int i = 0; i < 3; i++) {
            int idx = tid + i * 256;
            int row = idx >> 2, ch = idx & 3;
            cp16(&sB[row * SKA + ch * 8], &g_WAt[(size_t)row * PDIM + kt + ch * 8]);
        }
        cp_commit();
    };

    load_stage(0, ks0);
    load_stage(1, ks0 + 32);
    load_stage(2, ks0 + 64);

    const int arow = lane & 15, asel = (lane >> 4) << 3;
    const int brow = (lane & 7) + ((lane >> 4) << 3), bsel = ((lane >> 3) & 1) << 3;

    for (int it = 0; it < 16; it++) {
        if (it < 14) cp_wait2(); else if (it == 14) cp_wait1(); else cp_wait0();
        __syncthreads();
        if (it + 3 < 16) load_stage((it + 3) & 3, ks0 + (it + 3) * 32);

        __nv_bfloat16* sA = smem + (it & 3) * STG_E;
        __nv_bfloat16* sB = sA + 128 * SKA;
        #pragma unroll
        for (int ks = 0; ks < 32; ks += 16) {
            uint32_t a[2][4];
            #pragma unroll
            for (int mf = 0; mf < 2; mf++)
                ldsm4(a[mf][0], a[mf][1], a[mf][2], a[mf][3],
                      &sA[(wm * 32 + mf * 16 + arow) * SKA + ks + asel]);
            #pragma unroll
            for (int nt = 0; nt < 6; nt++) {
                uint32_t b0, b1, b2, b3;
                ldsm4(b0, b1, b2, b3,
                      &sB[(wn * 96 + nt * 16 + brow) * SKA + ks + bsel]);
                uint32_t bp0[2] = {b0, b1}, bp1[2] = {b2, b3};
                #pragma unroll
                for (int mf = 0; mf < 2; mf++) {
                    mma_bf16(acc[mf][nt * 2],     a[mf], bp0);
                    mma_bf16(acc[mf][nt * 2 + 1], a[mf], bp1);
                }
            }
        }
        __syncthreads();
    }

    float* out = &g_accp[(size_t)blockIdx.y * BDIM * ND];
    #pragma unroll
    for (int mf = 0; mf < 2; mf++)
        #pragma unroll
        for (int nf = 0; nf < 12; nf++) {
            int r = m0 + wm * 32 + mf * 16 + g;
            int c = wn * 96 + nf * 8 + tg * 2;
            *(float2*)&out[(size_t)r * ND + c]       = make_float2(acc[mf][nf][0], acc[mf][nf][1]);
            *(float2*)&out[(size_t)(r + 8) * ND + c] = make_float2(acc[mf][nf][2], acc[mf][nf][3]);
        }
}

// ---------------- k_finish3: all 3 refinement steps, 16 rows/block ----------------
// smem layout (bytes):
//   sG    bf16[192*192]           73728
//   sW2   f32 [128*68]            34816   (ow2, padded stride 68)
//   sW1c  f32 [10*128]             5120
//   sCw2  f32 [64*10]              2560
//   sb    f32 [336]                1344   (cb1|cb2|ob1|ob2|ow3)
//   sacc,sD,sds f32[16*192] each  36864
//   sh1c  f32 [16*64]              4096
//   scv,sdzc f32[16*12] each       1536
//   sa1   f32 [16*128]             8192
//   sdz2  f32 [16*64]              4096
// total ~172 KB
__global__ void __launch_bounds__(256) k_finish3(
    const float* __restrict__ cb1, const float* __restrict__ cw2,
    const float* __restrict__ cb2, const float* __restrict__ ow1,
    const float* __restrict__ ob1, const float* __restrict__ ow2,
    const float* __restrict__ ob2, const float* __restrict__ ow3) {
    extern __shared__ char sm[];
    __nv_bfloat16* sG = (__nv_bfloat16*)sm;
    float* sW2  = (float*)(sm + 73728);
    float* sW1c = sW2 + 128 * 68;
    float* sCw2 = sW1c + 1280;
    float* sb   = sCw2 + 640;
    float* sacc = sb + 336;
    float* sD   = sacc + FR * 192;
    float* sds  = sD + FR * 192;
    float* sh1c = sds + FR * 192;
    float* scv  = sh1c + FR * 64;
    float* sdzc = scv + FR * 12;
    float* sa1  = sdzc + FR * 12;
    float* sdz2 = sa1 + FR * 128;

    const int tid = threadIdx.x;
    const int b0 = blockIdx.x * FR;

    // ---- load weights once ----
    for (int i = tid; i < 192 * 96; i += 256) {             // G as float2 -> bf16x2
        float2 v = *(const float2*)&g_G[i * 2];
        ((__nv_bfloat162*)sG)[i] = __floats2bfloat162_rn(v.x, v.y);
    }
    for (int i = tid; i < 8192; i += 256) {
        int j = i >> 6, k = i & 63;
        sW2[j * 68 + k] = ow2[i];
    }
    for (int i = tid; i < 1280; i += 256) {
        int q = i >> 7, j = i & 127;
        sW1c[i] = ow1[(PDIM + q) * 128 + j];
    }
    for (int i = tid; i < 640; i += 256) sCw2[i] = cw2[i];
    if (tid < 64)  sb[tid]       = cb1[tid];
    if (tid < 10)  sb[64 + tid]  = cb2[tid];
    if (tid < 128) sb[80 + tid]  = ob1[tid];
    if (tid < 64)  sb[208 + tid] = ob2[tid];
    if (tid < 64)  sb[272 + tid] = ow3[tid];

    // ---- acc0 = sum of split-K partials; D = 0 ----
    for (int i = tid; i < FR * 192; i += 256) {
        int r = i / 192, n = i % 192;
        size_t bb = (size_t)(b0 + r);
        float s = 0.f;
        #pragma unroll
        for (int sp = 0; sp < NSPLIT; sp++)
            s += g_accp[((size_t)sp * BDIM + bb) * ND + n];
        sacc[i] = s;
        sD[i] = 0.f;
    }
    __syncthreads();

    for (int step = 0; step < 3; step++) {
        // h1c = relu(acc[:64] + cb1)
        for (int i = tid; i < FR * 64; i += 256) {
            int r = i >> 6, j = i & 63;
            sh1c[i] = fmaxf(sacc[r * 192 + j] + sb[j], 0.f);
        }
        __syncthreads();
        // cv = sigmoid(h1c @ cw2 + cb2)
        if (tid < FR * 10) {
            int r = tid / 10, q = tid % 10;
            float s = sb[64 + q];
            #pragma unroll 8
            for (int k = 0; k < 64; k++) s += sh1c[r * 64 + k] * sCw2[k * 10 + q];
            scv[r * 12 + q] = 1.f / (1.f + expf(-s));
        }
        __syncthreads();
        // a1 = relu(acc[64:] + ob1 + cv @ ow1[P:])
        for (int i = tid; i < FR * 128; i += 256) {
            int r = i >> 7, j = i & 127;
            float z = sacc[r * 192 + 64 + j] + sb[80 + j];
            #pragma unroll
            for (int q = 0; q < 10; q++) z += scv[r * 12 + q] * sW1c[q * 128 + j];
            sa1[i] = fmaxf(z, 0.f);
        }
        __syncthreads();
        // dz2 = relu'(a1 @ ow2 + ob2) * ow3
        for (int i = tid; i < FR * 64; i += 256) {
            int r = i >> 6, k = i & 63;
            float s = sb[208 + k];
            #pragma unroll 8
            for (int j = 0; j < 128; j++) s += sa1[r * 128 + j] * sW2[j * 68 + k];
            sdz2[i] = (s > 0.f) ? sb[272 + k] : 0.f;
        }
        __syncthreads();
        // dz1 = relu'(z1) * (dz2 @ ow2^T)  -> sds[64+j]
        for (int i = tid; i < FR * 128; i += 256) {
            int r = i >> 7, j = i & 127;
            float s = 0.f;
            #pragma unroll 8
            for (int k = 0; k < 64; k++) s += sdz2[r * 64 + k] * sW2[j * 68 + k];
            sds[r * 192 + 64 + j] = (sa1[r * 128 + j] > 0.f) ? s : 0.f;
        }
        __syncthreads();
        // dzc = (dz1 @ ow1c^T) * cv*(1-cv)
        if (tid < FR * 10) {
            int r = tid / 10, q = tid % 10;
            float s = 0.f;
            #pragma unroll 8
            for (int j = 0; j < 128; j++) s += sds[r * 192 + 64 + j] * sW1c[q * 128 + j];
            float c = scv[r * 12 + q];
            sdzc[r * 12 + q] = s * c * (1.f - c);
        }
        __syncthreads();
        // dconstr = relu'(z1c) * (dzc @ cw2^T) -> sds[0..64)
        for (int i = tid; i < FR * 64; i += 256) {
            int r = i >> 6, j = i & 63;
            float s = 0.f;
            #pragma unroll
            for (int q = 0; q < 10; q++) s += sdzc[r * 12 + q] * sCw2[j * 10 + q];
            sds[r * 192 + j] = (sacc[r * 192 + j] + sb[j] > 0.f) ? s : 0.f;
        }
        __syncthreads();
        // D += -0.01*ds ; acc += -0.01*(ds @ G) for steps 0,1
        if (step < 2) {
            for (int i = tid; i < FR * 192; i += 256) {
                int r = i / 192, n = i % 192;
                const float* dsr = &sds[r * 192];
                float a = 0.f;
                #pragma unroll 4
                for (int m = 0; m < 192; m++)
                    a += dsr[m] * __bfloat162float(sG[m * 192 + n]);
                sacc[i] += -0.01f * a;
                sD[i]   += -0.01f * dsr[n];
            }
        } else {
            for (int i = tid; i < FR * 192; i += 256) sD[i] += -0.01f * sds[i];
        }
        __syncthreads();
    }

    // write dcat (bf16, padded to SK2)
    for (int i = tid; i < FR * SK2; i += 256) {
        int r = i / SK2, n = i % SK2;
        g_dcat[(size_t)(b0 + r) * SK2 + n] =
            __float2bfloat16(n < 192 ? sD[r * 192 + n] : 0.f);
    }
}

// ---------------- GEMM2: out = params0 + D x Wcat^T ----------------
__global__ void __launch_bounds__(256) k_gemm2(float* __restrict__ outp) {
    extern __shared__ char smem_raw[];
    __nv_bfloat16* sA = (__nv_bfloat16*)smem_raw;          // 128 x 200
    __nv_bfloat16* sB = sA + 128 * SK2;                    // 128 x 200
    const int tid = threadIdx.x, lane = tid & 31, w = tid >> 5;
    const int wm = w >> 1, wn = w & 1, g = lane >> 2, tg = lane & 3;
    const int m0 = blockIdx.x * 128;
    const int n0 = blockIdx.y * 128;

    #pragma unroll
    for (int i = 0; i < 12; i++) {
        int idx = tid + i * 256;
        int row = idx / 24, ch = idx % 24;
        cp16(&sA[row * SK2 + ch * 8], &g_dcat[(size_t)(m0 + row) * SK2 + ch * 8]);
    }
    #pragma unroll
    for (int i = 0; i < 12; i++) {
        int idx = tid + i * 256;
        int row = idx / 24, ch = idx % 24;
        cp16(&sB[row * SK2 + ch * 8], &g_WBt[(size_t)(n0 + row) * SK2 + ch * 8]);
    }
    cp_commit();

    float acc[2][8][4];
    #pragma unroll
    for (int i = 0; i < 2; i++)
        #pragma unroll
        for (int j = 0; j < 8; j++)
            #pragma unroll
            for (int q = 0; q < 4; q++) acc[i][j][q] = 0.f;

    cp_wait0();
    __syncthreads();

    const int arow = lane & 15, asel = (lane >> 4) << 3;
    const int brow = (lane & 7) + ((lane >> 4) << 3), bsel = ((lane >> 3) & 1) << 3;

    #pragma unroll
    for (int ks = 0; ks < ND; ks += 16) {
        uint32_t a[2][4];
        #pragma unroll
        for (int mf = 0; mf < 2; mf++)
            ldsm4(a[mf][0], a[mf][1], a[mf][2], a[mf][3],
                  &sA[(wm * 32 + mf * 16 + arow) * SK2 + ks + asel]);
        #pragma unroll
        for (int nt = 0; nt < 4; nt++) {
            uint32_t b0, b1, b2, b3;
            ldsm4(b0, b1, b2, b3,
                  &sB[(wn * 64 + nt * 16 + brow) * SK2 + ks + bsel]);
            uint32_t bp0[2] = {b0, b1}, bp1[2] = {b2, b3};
            #pragma unroll
            for (int mf = 0; mf < 2; mf++) {
                mma_bf16(acc[mf][nt * 2],     a[mf], bp0);
                mma_bf16(acc[mf][nt * 2 + 1], a[mf], bp1);
            }
        }
    }

    #pragma unroll
    for (int mf = 0; mf < 2; mf++)
        #pragma unroll
        for (int nf = 0; nf < 8; nf++) {
            int r = m0 + wm * 32 + mf * 16 + g;
            int c = n0 + wn * 64 + nf * 8 + tg * 2;
            size_t i0 = (size_t)r * PDIM + c;
            size_t i1 = i0 + (size_t)8 * PDIM;
            float2 pv0 = *(const float2*)&g_params[i0];
            float2 pv1 = *(const float2*)&g_params[i1];
            *(float2*)&outp[i0] = make_float2(pv0.x + acc[mf][nf][0], pv0.y + acc[mf][nf][1]);
            *(float2*)&outp[i1] = make_float2(pv1.x + acc[mf][nf][2], pv1.y + acc[mf][nf][3]);
        }
}

// ---------------- launch ----------------
extern "C" void kernel_launch(void* const* d_in, const int* in_sizes, int n_in,
                              void* d_out, int out_size) {
    const float* tp   = (const float*)d_in[0];
    const float* cons = (const float*)d_in[1];
    // d_in[2] transverse_field, d_in[3] coupling, d_in[14] ob3 : dead
    const float* mp   = (const float*)d_in[4];
    const float* cw1  = (const float*)d_in[5];
    const float* cb1  = (const float*)d_in[6];
    const float* cw2  = (const float*)d_in[7];
    const float* cb2  = (const float*)d_in[8];
    const float* ow1  = (const float*)d_in[9];
    const float* ob1  = (const float*)d_in[10];
    const float* ow2  = (const float*)d_in[11];
    const float* ob2  = (const float*)d_in[12];
    const float* ow3  = (const float*)d_in[13];
    float* outp = (float*)d_out;

    const int SMEM1 = 4 * (128 * SKA + ND * SKA) * 2;   // 102400
    const int SMEM2 = 2 * 128 * SK2 * 2;                // 102400
    const int SMEMF = 73728 + (128 * 68 + 1280 + 640 + 336 + 3 * FR * 192 +
                               FR * 64 + 2 * FR * 12 + FR * 128 + FR * 64) * 4;
    cudaFuncSetAttribute(k_gemm1,   cudaFuncAttributeMaxDynamicSharedMemorySize, SMEM1);
    cudaFuncSetAttribute(k_gemm2,   cudaFuncAttributeMaxDynamicSharedMemorySize, SMEM2);
    cudaFuncSetAttribute(k_finish3, cudaFuncAttributeMaxDynamicSharedMemorySize, SMEMF);

    k_setup<<<NB_CM + NB_GRAM + NB_PREP, 256>>>(mp, cw1, ow1);
    k_init<<<(BDIM * PDIM / 4) / 256, 256>>>(tp, cons);
    k_gemm1<<<dim3(16, NSPLIT), 256, SMEM1>>>();
    k_finish3<<<BDIM / FR, 256, SMEMF>>>(cb1, cw2, cb2, ow1, ob1, ow2, ob2, ow3);
    k_gemm2<<<dim3(16, 32), 256, SMEM2>>>(outp);
}

// round 5
// speedup vs baseline: 1.8870x; 1.1441x over previous
#include <cuda_runtime.h>
#include <cuda_bf16.h>
#include <cstdint>

#define BDIM 2048
#define PDIM 4096
#define PD_TP 4086
#define CONS 10
#define QDIM 1024
#define ND 192          // Wcat columns: [0,64)=cw1, [64,192)=ow1[:P]
#define SK2 200         // gemm2 padded k-stride (elems)
#define SKA 40          // gemm1 smem k-stride (elems)
#define NSPLIT 16       // gemm1 split-K
#define FR 16           // finish3 rows per block

// ---------------- device scratch (allocation-free) ----------------
__device__ __align__(256) float          g_m[PDIM];
__device__ __align__(256) float          g_G[ND * ND];                        // Gram Wcat^T Wcat
__device__ __align__(256) float          g_params[(size_t)BDIM * PDIM];       // params0 fp32
__device__ __align__(256) __nv_bfloat16  g_pbf[(size_t)BDIM * PDIM];          // params0 bf16
__device__ __align__(256) __nv_bfloat16  g_WAt[(size_t)ND * PDIM];            // Wcat^T [n][k]
__device__ __align__(256) __nv_bfloat16  g_WBt[(size_t)PDIM * SK2];           // Wcat   [p][n pad]
__device__ __align__(256) float          g_accp[(size_t)NSPLIT * BDIM * ND];  // gemm1 partials
__device__ __align__(256) __nv_bfloat16  g_dcat[(size_t)BDIM * SK2];          // final D bf16

// ---------------- helpers ----------------
__device__ __forceinline__ void cp16(void* s, const void* g) {
    uint32_t sa = (uint32_t)__cvta_generic_to_shared(s);
    asm volatile("cp.async.cg.shared.global [%0], [%1], 16;\n" :: "r"(sa), "l"(g));
}
__device__ __forceinline__ void cp_commit() { asm volatile("cp.async.commit_group;\n"); }
__device__ __forceinline__ void cp_wait0()  { asm volatile("cp.async.wait_group 0;\n"); }
__device__ __forceinline__ void cp_wait1()  { asm volatile("cp.async.wait_group 1;\n"); }

__device__ __forceinline__ void mma_bf16(float* c, const uint32_t* a, const uint32_t* b) {
    asm volatile(
        "mma.sync.aligned.m16n8k16.row.col.f32.bf16.bf16.f32 "
        "{%0,%1,%2,%3},{%4,%5,%6,%7},{%8,%9},{%0,%1,%2,%3};\n"
        : "+f"(c[0]), "+f"(c[1]), "+f"(c[2]), "+f"(c[3])
        : "r"(a[0]), "r"(a[1]), "r"(a[2]), "r"(a[3]), "r"(b[0]), "r"(b[1]));
}
__device__ __forceinline__ void ldsm4(uint32_t& r0, uint32_t& r1, uint32_t& r2, uint32_t& r3,
                                      const void* p) {
    uint32_t a = (uint32_t)__cvta_generic_to_shared(p);
    asm volatile("ldmatrix.sync.aligned.m8n8.x4.shared.b16 {%0,%1,%2,%3},[%4];\n"
                 : "=r"(r0), "=r"(r1), "=r"(r2), "=r"(r3) : "r"(a));
}
__device__ __forceinline__ float ftanh(float x) {
    float y; asm("tanh.approx.f32 %0, %1;\n" : "=f"(y) : "f"(x)); return y;
}

// ---------------- k_setup: colmean + gram + prepw in one launch ----------------
#define NB_CM   128
#define NB_GRAM 36
#define NB_PREP 6272
__global__ void __launch_bounds__(256) k_setup(const float* __restrict__ mp,
                                               const float* __restrict__ cw1,
                                               const float* __restrict__ ow1) {
    __shared__ float sbuf[4096];
    const int blk = blockIdx.x, tid = threadIdx.x;

    if (blk < NB_CM) {
        int p = blk * 32 + (tid & 31);
        int qi = tid >> 5;
        float s = 0.f;
        #pragma unroll 8
        for (int q = qi * 128; q < qi * 128 + 128; q++)
            s += mp[(size_t)q * PDIM + p];
        sbuf[qi * 32 + (tid & 31)] = s;
        __syncthreads();
        if (tid < 32) {
            float t = 0.f;
            #pragma unroll
            for (int r = 0; r < 8; r++) t += sbuf[r * 32 + tid];
            g_m[blk * 32 + tid] = t * (1.0f / QDIM);
        }
        return;
    }

    if (blk < NB_CM + NB_GRAM) {
        float* sA = sbuf;
        float* sB = sbuf + 2048;
        int gb = blk - NB_CM;
        int i0 = (gb / 6) * 32, j0 = (gb % 6) * 32;
        int tx = tid & 15, ty = tid >> 4;
        float c00 = 0.f, c01 = 0.f, c10 = 0.f, c11 = 0.f;
        for (int kc = 0; kc < 64; kc++) {
            int kb = kc * 64;
            #pragma unroll
            for (int r = 0; r < 8; r++) {
                int idx = tid + r * 256;
                int kk = idx >> 5, cc = idx & 31;
                int ci = i0 + cc, cj = j0 + cc, k = kb + kk;
                sA[kk * 32 + cc] = (ci < 64) ? cw1[k * 64 + ci] : ow1[k * 128 + ci - 64];
                sB[kk * 32 + cc] = (cj < 64) ? cw1[k * 64 + cj] : ow1[k * 128 + cj - 64];
            }
            __syncthreads();
            #pragma unroll 8
            for (int k = 0; k < 64; k++) {
                float a0 = sA[k * 32 + 2 * tx], a1 = sA[k * 32 + 2 * tx + 1];
                float b0 = sB[k * 32 + 2 * ty], b1 = sB[k * 32 + 2 * ty + 1];
                c00 += a0 * b0; c01 += a0 * b1;
                c10 += a1 * b0; c11 += a1 * b1;
            }
            __syncthreads();
        }
        int gi = i0 + 2 * tx, gj = j0 + 2 * ty;
        g_G[gi * ND + gj]           = c00;
        g_G[gi * ND + gj + 1]       = c01;
        g_G[(gi + 1) * ND + gj]     = c10;
        g_G[(gi + 1) * ND + gj + 1] = c11;
        return;
    }

    int idx = (blk - NB_CM - NB_GRAM) * 256 + tid;
    const int T1 = ND * PDIM;
    if (idx < T1) {
        int n = idx / PDIM, k = idx % PDIM;
        float v = (n < 64) ? cw1[k * 64 + n] : ow1[k * 128 + (n - 64)];
        g_WAt[idx] = __float2bfloat16(v);
    } else {
        int j = idx - T1;
        int p = j / SK2, q = j % SK2;
        float v = 0.f;
        if (q < 64)       v = cw1[p * 64 + q];
        else if (q < ND)  v = ow1[p * 128 + (q - 64)];
        g_WBt[j] = __float2bfloat16(v);
    }
}

// ---------------- params0 = tanh(0.7*colmean + 0.3*enc) ----------------
__global__ void __launch_bounds__(256) k_init(const float* __restrict__ tp,
                                              const float* __restrict__ cons) {
    int idx = blockIdx.x * 256 + threadIdx.x;
    int b = idx >> 10;
    int pg = (idx & 1023) << 2;
    const float* trow = tp + (size_t)b * PD_TP;
    float e0, e1, e2, e3;
    if (pg + 3 < PD_TP) {
        float2 u = *(const float2*)(trow + pg);
        float2 v2 = *(const float2*)(trow + pg + 2);
        e0 = u.x; e1 = u.y; e2 = v2.x; e3 = v2.y;
    } else if (pg < PD_TP) {
        float2 u = *(const float2*)(trow + pg);
        e0 = u.x; e1 = u.y;
        e2 = cons[b * CONS + 0]; e3 = cons[b * CONS + 1];
    } else {
        int c0 = pg - PD_TP;
        e0 = cons[b * CONS + c0];     e1 = cons[b * CONS + c0 + 1];
        e2 = cons[b * CONS + c0 + 2]; e3 = cons[b * CONS + c0 + 3];
    }
    float4 m4 = *(const float4*)&g_m[pg];
    float v0 = ftanh(0.7f * m4.x + 0.3f * e0);
    float v1 = ftanh(0.7f * m4.y + 0.3f * e1);
    float v2_ = ftanh(0.7f * m4.z + 0.3f * e2);
    float v3 = ftanh(0.7f * m4.w + 0.3f * e3);
    size_t o = (size_t)b * PDIM + pg;
    *(float4*)&g_params[o] = make_float4(v0, v1, v2_, v3);
    union { __nv_bfloat162 h[2]; uint2 u; } pk;
    pk.h[0] = __floats2bfloat162_rn(v0, v1);
    pk.h[1] = __floats2bfloat162_rn(v2_, v3);
    *(uint2*)&g_pbf[o] = pk.u;
}

// ---------------- GEMM1: accp = pbf x WAt^T, split-K=16, 3-stage ring ----------------
__global__ void __launch_bounds__(256, 2) k_gemm1() {
    extern __shared__ char smem_raw[];
    __nv_bfloat16* smem = (__nv_bfloat16*)smem_raw;
    const int STG_E = 128 * SKA + ND * SKA;    // 12800 elems/stage
    const int tid = threadIdx.x, lane = tid & 31, w = tid >> 5;
    const int wm = w >> 1, wn = w & 1, g = lane >> 2, tg = lane & 3;
    const int m0 = blockIdx.x * 128;
    const int ks0 = blockIdx.y * 256;          // K chunk 256 -> 8 iters of 32

    float acc[2][12][4];
    #pragma unroll
    for (int i = 0; i < 2; i++)
        #pragma unroll
        for (int j = 0; j < 12; j++)
            #pragma unroll
            for (int q = 0; q < 4; q++) acc[i][j][q] = 0.f;

    auto load_stage = [&](int st, int kt) {
        __nv_bfloat16* sA = smem + st * STG_E;
        __nv_bfloat16* sB = sA + 128 * SKA;
        #pragma unroll
        for (int i = 0; i < 2; i++) {
            int idx = tid + i * 256;
            int row = idx >> 2, ch = idx & 3;
            cp16(&sA[row * SKA + ch * 8], &g_pbf[(size_t)(m0 + row) * PDIM + kt + ch * 8]);
        }
        #pragma unroll
        for (int i = 0; i < 3; i++) {
            int idx = tid + i * 256;
            int row = idx >> 2, ch = idx & 3;
            cp16(&sB[row * SKA + ch * 8], &g_WAt[(size_t)row * PDIM + kt + ch * 8]);
        }
        cp_commit();
    };

    load_stage(0, ks0);
    load_stage(1, ks0 + 32);

    const int arow = lane & 15, asel = (lane >> 4) << 3;
    const int brow = (lane & 7) + ((lane >> 4) << 3), bsel = ((lane >> 3) & 1) << 3;

    for (int it = 0; it < 8; it++) {
        if (it < 7) cp_wait1(); else cp_wait0();
        __syncthreads();
        if (it + 2 < 8) load_stage((it + 2) % 3, ks0 + (it + 2) * 32);

        __nv_bfloat16* sA = smem + (it % 3) * STG_E;
        __nv_bfloat16* sB = sA + 128 * SKA;
        #pragma unroll
        for (int ks = 0; ks < 32; ks += 16) {
            uint32_t a[2][4];
            #pragma unroll
            for (int mf = 0; mf < 2; mf++)
                ldsm4(a[mf][0], a[mf][1], a[mf][2], a[mf][3],
                      &sA[(wm * 32 + mf * 16 + arow) * SKA + ks + asel]);
            #pragma unroll
            for (int nt = 0; nt < 6; nt++) {
                uint32_t b0, b1, b2, b3;
                ldsm4(b0, b1, b2, b3,
                      &sB[(wn * 96 + nt * 16 + brow) * SKA + ks + bsel]);
                uint32_t bp0[2] = {b0, b1}, bp1[2] = {b2, b3};
                #pragma unroll
                for (int mf = 0; mf < 2; mf++) {
                    mma_bf16(acc[mf][nt * 2],     a[mf], bp0);
                    mma_bf16(acc[mf][nt * 2 + 1], a[mf], bp1);
                }
            }
        }
        __syncthreads();
    }

    float* out = &g_accp[(size_t)blockIdx.y * BDIM * ND];
    #pragma unroll
    for (int mf = 0; mf < 2; mf++)
        #pragma unroll
        for (int nf = 0; nf < 12; nf++) {
            int r = m0 + wm * 32 + mf * 16 + g;
            int c = wn * 96 + nf * 8 + tg * 2;
            *(float2*)&out[(size_t)r * ND + c]       = make_float2(acc[mf][nf][0], acc[mf][nf][1]);
            *(float2*)&out[(size_t)(r + 8) * ND + c] = make_float2(acc[mf][nf][2], acc[mf][nf][3]);
        }
}

// ---------------- k_finish3: 3 refinement steps, 16 rows/block, 512 threads ----------------
// smem offsets (bytes), all 16B aligned:
#define OFF_G    0
#define OFF_W2   73728
#define OFF_W1C  108544
#define OFF_CW2  113664
#define OFF_B    116224
#define OFF_ACC  117568
#define OFF_DS   129856
#define OFF_D    142144
#define OFF_H1C  154432
#define OFF_CV   158528
#define OFF_DZC  159296
#define OFF_A1   160064
#define OFF_DZ2  168256
#define SMEMF    172352
__global__ void __launch_bounds__(512) k_finish3(
    const float* __restrict__ cb1, const float* __restrict__ cw2,
    const float* __restrict__ cb2, const float* __restrict__ ow1,
    const float* __restrict__ ob1, const float* __restrict__ ow2,
    const float* __restrict__ ob2, const float* __restrict__ ow3) {
    extern __shared__ char sm[];
    __nv_bfloat16* sG = (__nv_bfloat16*)(sm + OFF_G);   // [192][192]
    float* sW2  = (float*)(sm + OFF_W2);                // [128][68] ow2 padded
    float* sW1c = (float*)(sm + OFF_W1C);               // [10][128] ow1[P:]
    float* sCw2 = (float*)(sm + OFF_CW2);               // [64][10]
    float* sb   = (float*)(sm + OFF_B);                 // cb1|cb2|ob1|ob2|ow3
    float* sacc = (float*)(sm + OFF_ACC);               // [16][192]
    float* sds  = (float*)(sm + OFF_DS);                // [16][192]
    float* sD   = (float*)(sm + OFF_D);                 // [16][192]
    float* sh1c = (float*)(sm + OFF_H1C);               // [16][64]
    float* scv  = (float*)(sm + OFF_CV);                // [16][12]
    float* sdzc = (float*)(sm + OFF_DZC);               // [16][12]
    float* sa1  = (float*)(sm + OFF_A1);                // [16][128]
    float* sdz2 = (float*)(sm + OFF_DZ2);               // [16][64]

    const int tid = threadIdx.x;
    const int b0 = blockIdx.x * FR;

    // ---- load weights once ----
    for (int i = tid; i < 192 * 96; i += 512) {
        float2 v = *(const float2*)&g_G[i * 2];
        ((__nv_bfloat162*)sG)[i] = __floats2bfloat162_rn(v.x, v.y);
    }
    for (int i = tid; i < 8192; i += 512) {
        int j = i >> 6, k = i & 63;
        sW2[j * 68 + k] = ow2[i];
    }
    for (int i = tid; i < 1280; i += 512) {
        int q = i >> 7, j = i & 127;
        sW1c[i] = ow1[(PDIM + q) * 128 + j];
    }
    for (int i = tid; i < 640; i += 512) sCw2[i] = cw2[i];
    if (tid < 64)  sb[tid]       = cb1[tid];
    if (tid < 10)  sb[64 + tid]  = cb2[tid];
    if (tid < 128) sb[80 + tid]  = ob1[tid];
    if (tid < 64)  sb[208 + tid] = ob2[tid];
    if (tid < 64)  sb[272 + tid] = ow3[tid];

    // ---- acc0 = sum of split-K partials (float4); D = 0 ----
    for (int i = tid; i < FR * 48; i += 512) {
        int r = i / 48, n4 = (i % 48) * 4;
        size_t bb = (size_t)(b0 + r);
        float4 s = make_float4(0.f, 0.f, 0.f, 0.f);
        #pragma unroll
        for (int sp = 0; sp < NSPLIT; sp++) {
            float4 v = *(const float4*)&g_accp[((size_t)sp * BDIM + bb) * ND + n4];
            s.x += v.x; s.y += v.y; s.z += v.z; s.w += v.w;
        }
        *(float4*)&sacc[r * 192 + n4] = s;
    }
    for (int i = tid; i < FR * 192; i += 512) sD[i] = 0.f;
    __syncthreads();

    for (int step = 0; step < 3; step++) {
        // h1c = relu(acc[:64] + cb1)
        for (int i = tid; i < FR * 64; i += 512) {
            int r = i >> 6, j = i & 63;
            sh1c[i] = fmaxf(sacc[r * 192 + j] + sb[j], 0.f);
        }
        __syncthreads();
        // cv = sigmoid(h1c @ cw2 + cb2)
        if (tid < FR * 10) {
            int r = tid / 10, q = tid % 10;
            float s = sb[64 + q];
            #pragma unroll 8
            for (int k = 0; k < 64; k++) s += sh1c[r * 64 + k] * sCw2[k * 10 + q];
            scv[r * 12 + q] = 1.f / (1.f + expf(-s));
        }
        __syncthreads();
        // a1 = relu(acc[64:] + ob1 + cv @ ow1[P:])
        for (int i = tid; i < FR * 128; i += 512) {
            int r = i >> 7, j = i & 127;
            float z = sacc[r * 192 + 64 + j] + sb[80 + j];
            #pragma unroll
            for (int q = 0; q < 10; q++) z += scv[r * 12 + q] * sW1c[q * 128 + j];
            sa1[i] = fmaxf(z, 0.f);
        }
        __syncthreads();
        // dz2 = relu'(a1 @ ow2 + ob2) * ow3   (k-pairs, float2 W2 loads)
        {
            int r = tid >> 5, kp = tid & 31;     // 512 = 16r x 32 kpairs
            int k2 = kp * 2;
            float s0 = sb[208 + k2], s1 = sb[208 + k2 + 1];
            const float* a1r = &sa1[r * 128];
            #pragma unroll 8
            for (int j = 0; j < 128; j++) {
                float a = a1r[j];
                float2 wv = *(const float2*)&sW2[j * 68 + k2];
                s0 += a * wv.x; s1 += a * wv.y;
            }
            sdz2[r * 64 + k2]     = (s0 > 0.f) ? sb[272 + k2] : 0.f;
            sdz2[r * 64 + k2 + 1] = (s1 > 0.f) ? sb[272 + k2 + 1] : 0.f;
        }
        __syncthreads();
        // dz1 = relu'(z1)*(dz2 @ ow2^T), scaled by -0.01 -> sds[64+j]  (float4)
        for (int s4 = 0; s4 < 4; s4++) {
            int i = tid + s4 * 512;             // 2048 outputs
            int r = i >> 7, j = i & 127;
            const float* dzr = &sdz2[r * 64];
            const float* wr = &sW2[j * 68];
            float s = 0.f;
            #pragma unroll
            for (int k = 0; k < 64; k += 4) {
                float4 dv = *(const float4*)&dzr[k];
                float4 wv = *(const float4*)&wr[k];
                s += dv.x * wv.x + dv.y * wv.y + dv.z * wv.z + dv.w * wv.w;
            }
            sds[r * 192 + 64 + j] = (sa1[i] > 0.f) ? -0.01f * s : 0.f;
        }
        __syncthreads();
        // dzc = (dz1 @ ow1c^T) * cv*(1-cv)   (carries -0.01 from sds)
        if (tid < FR * 10) {
            int r = tid / 10, q = tid % 10;
            const float* dsr = &sds[r * 192 + 64];
            const float* wr = &sW1c[q * 128];
            float s = 0.f;
            #pragma unroll
            for (int j = 0; j < 128; j += 4) {
                float4 dv = *(const float4*)&dsr[j];
                float4 wv = *(const float4*)&wr[j];
                s += dv.x * wv.x + dv.y * wv.y + dv.z * wv.z + dv.w * wv.w;
            }
            float c = scv[r * 12 + q];
            sdzc[r * 12 + q] = s * c * (1.f - c);
        }
        __syncthreads();
        // dconstr = relu'(z1c) * (dzc @ cw2^T) -> sds[0..64)  (carries -0.01)
        for (int i = tid; i < FR * 64; i += 512) {
            int r = i >> 6, j = i & 63;
            float s = 0.f;
            #pragma unroll
            for (int q = 0; q < 10; q++) s += sdzc[r * 12 + q] * sCw2[j * 10 + q];
            sds[r * 192 + j] = (sacc[r * 192 + j] + sb[j] > 0.f) ? s : 0.f;
        }
        __syncthreads();
        // D += ds (already -0.01-scaled)
        for (int i = tid; i < FR * 192; i += 512) sD[i] += sds[i];
        // acc += ds @ G for steps 0,1  (uint2 G loads: 4 bf16 per LDS)
        if (step < 2) {
            for (int i = tid; i < FR * 48; i += 512) {
                int r = i / 48, n4 = (i % 48) * 4;
                const float* dsr = &sds[r * 192];
                float a0 = 0.f, a1 = 0.f, a2 = 0.f, a3 = 0.f;
                #pragma unroll 4
                for (int m = 0; m < 192; m++) {
                    float d = dsr[m];
                    uint2 gv = *(const uint2*)&sG[m * 192 + n4];
                    __nv_bfloat162 g01 = *(__nv_bfloat162*)&gv.x;
                    __nv_bfloat162 g23 = *(__nv_bfloat162*)&gv.y;
                    a0 += d * __bfloat162float(g01.x);
                    a1 += d * __bfloat162float(g01.y);
                    a2 += d * __bfloat162float(g23.x);
                    a3 += d * __bfloat162float(g23.y);
                }
                float* ap = &sacc[r * 192 + n4];
                ap[0] += a0; ap[1] += a1; ap[2] += a2; ap[3] += a3;
            }
        }
        __syncthreads();
    }

    // write dcat (bf16, padded to SK2)
    for (int i = tid; i < FR * SK2; i += 512) {
        int r = i / SK2, n = i % SK2;
        g_dcat[(size_t)(b0 + r) * SK2 + n] =
            __float2bfloat16(n < 192 ? sD[r * 192 + n] : 0.f);
    }
}

// ---------------- GEMM2: out = params0 + D x Wcat^T, n-tile 64 ----------------
__global__ void __launch_bounds__(256, 2) k_gemm2(float* __restrict__ outp) {
    extern __shared__ char smem_raw[];
    __nv_bfloat16* sA = (__nv_bfloat16*)smem_raw;          // 128 x 200
    __nv_bfloat16* sB = sA + 128 * SK2;                    // 64 x 200
    const int tid = threadIdx.x, lane = tid & 31, w = tid >> 5;
    const int wm = w >> 1, wn = w & 1, g = lane >> 2, tg = lane & 3;
    const int m0 = blockIdx.x * 128;
    const int n0 = blockIdx.y * 64;

    #pragma unroll
    for (int i = 0; i < 12; i++) {           // A: 3072 16B chunks
        int idx = tid + i * 256;
        int row = idx / 24, ch = idx % 24;
        cp16(&sA[row * SK2 + ch * 8], &g_dcat[(size_t)(m0 + row) * SK2 + ch * 8]);
    }
    for (int idx = tid; idx < 1600; idx += 256) {  // B: 64 rows x 25 chunks
        int row = idx / 25, ch = idx % 25;
        if (ch < 24)
            cp16(&sB[row * SK2 + ch * 8], &g_WBt[(size_t)(n0 + row) * SK2 + ch * 8]);
    }
    cp_commit();

    float acc[2][4][4];
    #pragma unroll
    for (int i = 0; i < 2; i++)
        #pragma unroll
        for (int j = 0; j < 4; j++)
            #pragma unroll
            for (int q = 0; q < 4; q++) acc[i][j][q] = 0.f;

    cp_wait0();
    __syncthreads();

    const int arow = lane & 15, asel = (lane >> 4) << 3;
    const int brow = (lane & 7) + ((lane >> 4) << 3), bsel = ((lane >> 3) & 1) << 3;

    #pragma unroll
    for (int ks = 0; ks < ND; ks += 16) {
        uint32_t a[2][4];
        #pragma unroll
        for (int mf = 0; mf < 2; mf++)
            ldsm4(a[mf][0], a[mf][1], a[mf][2], a[mf][3],
                  &sA[(wm * 32 + mf * 16 + arow) * SK2 + ks + asel]);
        #pragma unroll
        for (int nt = 0; nt < 2; nt++) {
            uint32_t b0, b1, b2, b3;
            ldsm4(b0, b1, b2, b3,
                  &sB[(wn * 32 + nt * 16 + brow) * SK2 + ks + bsel]);
            uint32_t bp0[2] = {b0, b1}, bp1[2] = {b2, b3};
            #pragma unroll
            for (int mf = 0; mf < 2; mf++) {
                mma_bf16(acc[mf][nt * 2],     a[mf], bp0);
                mma_bf16(acc[mf][nt * 2 + 1], a[mf], bp1);
            }
        }
    }

    #pragma unroll
    for (int mf = 0; mf < 2; mf++)
        #pragma unroll
        for (int nf = 0; nf < 4; nf++) {
            int r = m0 + wm * 32 + mf * 16 + g;
            int c = n0 + wn * 32 + nf * 8 + tg * 2;
            size_t i0 = (size_t)r * PDIM + c;
            size_t i1 = i0 + (size_t)8 * PDIM;
            float2 pv0 = *(const float2*)&g_params[i0];
            float2 pv1 = *(const float2*)&g_params[i1];
            *(float2*)&outp[i0] = make_float2(pv0.x + acc[mf][nf][0], pv0.y + acc[mf][nf][1]);
            *(float2*)&outp[i1] = make_float2(pv1.x + acc[mf][nf][2], pv1.y + acc[mf][nf][3]);
        }
}

// ---------------- launch ----------------
extern "C" void kernel_launch(void* const* d_in, const int* in_sizes, int n_in,
                              void* d_out, int out_size) {
    const float* tp   = (const float*)d_in[0];
    const float* cons = (const float*)d_in[1];
    // d_in[2] transverse_field, d_in[3] coupling, d_in[14] ob3 : dead
    const float* mp   = (const float*)d_in[4];
    const float* cw1  = (const float*)d_in[5];
    const float* cb1  = (const float*)d_in[6];
    const float* cw2  = (const float*)d_in[7];
    const float* cb2  = (const float*)d_in[8];
    const float* ow1  = (const float*)d_in[9];
    const float* ob1  = (const float*)d_in[10];
    const float* ow2  = (const float*)d_in[11];
    const float* ob2  = (const float*)d_in[12];
    const float* ow3  = (const float*)d_in[13];
    float* outp = (float*)d_out;

    const int SMEM1 = 3 * (128 * SKA + ND * SKA) * 2;   // 76800
    const int SMEM2 = (128 * SK2 + 64 * SK2) * 2;       // 76800
    cudaFuncSetAttribute(k_gemm1,   cudaFuncAttributeMaxDynamicSharedMemorySize, SMEM1);
    cudaFuncSetAttribute(k_gemm2,   cudaFuncAttributeMaxDynamicSharedMemorySize, SMEM2);
    cudaFuncSetAttribute(k_finish3, cudaFuncAttributeMaxDynamicSharedMemorySize, SMEMF);

    k_setup<<<NB_CM + NB_GRAM + NB_PREP, 256>>>(mp, cw1, ow1);
    k_init<<<(BDIM * PDIM / 4) / 256, 256>>>(tp, cons);
    k_gemm1<<<dim3(16, NSPLIT), 256, SMEM1>>>();
    k_finish3<<<BDIM / FR, 512, SMEMF>>>(cb1, cw2, cb2, ow1, ob1, ow2, ob2, ow3);
    k_gemm2<<<dim3(16, 64), 256, SMEM2>>>(outp);
}